// round 14
// baseline (speedup 1.0000x reference)
#include <cuda_runtime.h>
#include <cuda_bf16.h>
#include <math.h>
#include <stdint.h>

// ---------------- problem constants ----------------
#define TT  32      // timesteps
#define BB  64      // batch
#define HH  512     // hidden
#define EE  512     // embed
#define MLL 64      // encoder length
#define VV  32000   // vocab
#define NL  2       // lstm layers
#define KP  1536    // vocab split-bf16 K (3 x 512)
#define KR  3072    // recurrence split-bf16 K (3 x 1024)
#define LDA 40      // padded smem row (bf16 units)
#define NREC 64     // recurrence blocks (grid-barrier population)
#define NGRID 148   // total blocks = #SMs -> one block per SM
#define ZR  16      // rnn_in K-split planes
#define ZG  4       // gate K-split planes
#define NTILE_N 250           // 32000/128 vocab n-tiles
#define NTILE_M 16            // 2048/128 vocab m-tiles
#define NT_TOT (NTILE_M * NTILE_N)   // 4000 vocab tiles (128x128)

// ---------------- persistent device state ----------------
__device__ float g_h[NL][BB][HH];
__device__ float g_c[NL][BB][HH];
__device__ float g_rp[ZR][BB][EE];            // rnn_in K-split partials
__device__ float g_gp[ZG][BB][4 * HH];        // gate K-split partials
__device__ __nv_bfloat16 g_A1[BB][KR];        // cat2 split [emb|ctx]
__device__ __nv_bfloat16 g_GA[NL][BB][KR];    // gate input split per layer [x|h]
__device__ __nv_bfloat16 g_AOW[EE][KR];       // attn_out_W split
__device__ __nv_bfloat16 g_GW[NL][4 * HH][KR];// [Wi_l | Wh_l] split
__device__ __nv_bfloat16 g_Ap[(size_t)TT * BB * KP];   // vocab A'
__device__ __nv_bfloat16 g_Wp[(size_t)VV * KP];        // vocab W'

// sync / queue state
__device__ unsigned g_barc;
__device__ volatile unsigned g_barg;
__device__ unsigned g_vtile;           // vocab tile queue head
__device__ volatile unsigned g_done;   // completed steps

__device__ __forceinline__ float sigf(float x) { return 1.0f / (1.0f + expf(-x)); }

__device__ __forceinline__ uint32_t smem_u32(const void* p) {
    uint32_t a;
    asm("{ .reg .u64 t; cvta.to.shared.u64 t, %1; cvt.u32.u64 %0, t; }" : "=r"(a) : "l"(p));
    return a;
}

__device__ __forceinline__ void bsplit(float v, __nv_bfloat16& hi, __nv_bfloat16& lo) {
    hi = __float2bfloat16_rn(v);
    lo = __float2bfloat16_rn(v - __bfloat162float(hi));
}

// grid barrier over blocks 0..NREC-1 (recurrence only)
__device__ __forceinline__ void gridbar() {
    __syncthreads();
    if (threadIdx.x == 0) {
        unsigned g = g_barg;
        __threadfence();
        if (atomicAdd(&g_barc, 1u) == NREC - 1) {
            g_barc = 0;
            __threadfence();
            g_barg = g + 1;
        } else {
            while (g_barg == g) {}
            __threadfence();
        }
    }
    __syncthreads();
}

// ---------------- init: state copy + h split + queue reset ----------------
__global__ void k_init(const float* __restrict__ h0, const float* __restrict__ c0) {
    int i = blockIdx.x * 256 + threadIdx.x;
    if (i == 0) { g_vtile = 0; g_done = 0; }
    if (i < NL * BB * HH) {
        ((float*)g_h)[i] = h0[i];
        ((float*)g_c)[i] = c0[i];
        int l = i >> 15, r = i & 32767;
        int b = r >> 9, h = r & 511;
        __nv_bfloat16 hi, lo;
        bsplit(h0[i], hi, lo);
        g_GA[l][b][512 + h]  = hi;
        g_GA[l][b][1536 + h] = hi;
        g_GA[l][b][2560 + h] = lo;
    }
}

// ================= recurrence phases (256 threads) =================

__device__ void ph_attn(int b, const int* __restrict__ tok,
                        const float* __restrict__ emb,
                        const float* __restrict__ attn_W,
                        const float* __restrict__ enc,
                        float* av, float* sc)
{
    int tid = threadIdx.x;
    int t = tok[b];
    const float* er = emb + (size_t)t * EE;
    for (int i = tid; i < EE; i += 256) {
        float v = er[i];
        av[i] = v;
        __nv_bfloat16 hi, lo;
        bsplit(v, hi, lo);
        g_A1[b][i] = hi; g_A1[b][1024 + i] = hi; g_A1[b][2048 + i] = lo;
    }
    const float* hr = &g_h[NL - 1][b][0];
    for (int i = tid; i < HH; i += 256) av[EE + i] = hr[i];
    __syncthreads();

    int w = tid >> 5, lane = tid & 31;
    for (int m = w; m < MLL; m += 8) {
        const float* wr = attn_W + (size_t)m * (EE + HH);
        float s = 0.f;
        #pragma unroll 8
        for (int k = lane; k < EE + HH; k += 32) s = fmaf(av[k], wr[k], s);
        #pragma unroll
        for (int o = 16; o; o >>= 1) s += __shfl_xor_sync(0xffffffffu, s, o);
        if (lane == 0) sc[m] = s;
    }
    __syncthreads();

    if (tid < 32) {
        float a0 = sc[tid], a1 = sc[tid + 32];
        float m = fmaxf(a0, a1);
        #pragma unroll
        for (int o = 16; o; o >>= 1) m = fmaxf(m, __shfl_xor_sync(0xffffffffu, m, o));
        float e0 = expf(a0 - m), e1 = expf(a1 - m);
        float s = e0 + e1;
        #pragma unroll
        for (int o = 16; o; o >>= 1) s += __shfl_xor_sync(0xffffffffu, s, o);
        float inv = 1.0f / s;
        sc[tid] = e0 * inv;
        sc[tid + 32] = e1 * inv;
    }
    __syncthreads();

    for (int h = tid; h < HH; h += 256) {
        float acc = 0.f;
        #pragma unroll 8
        for (int m = 0; m < MLL; m++)
            acc = fmaf(sc[m], enc[((size_t)m * BB + b) * HH + h], acc);
        __nv_bfloat16 hi, lo;
        bsplit(acc, hi, lo);
        g_A1[b][512 + h] = hi; g_A1[b][1536 + h] = hi; g_A1[b][2560 + h] = lo;
    }
    __syncthreads();
}

// K-sliced recurrence GEMM tile (M=64): C[z][64][Ntot] cols n0..n0+127
__device__ void ph_rgemm(const __nv_bfloat16* __restrict__ A,
                         const __nv_bfloat16* __restrict__ W,
                         int Ntot, float* __restrict__ Cp,
                         int ntile, int z, int nch, int kst, char* smraw)
{
    __nv_bfloat16* sA = (__nv_bfloat16*)smraw;     // [2][64*LDA]
    __nv_bfloat16* sB = sA + 2 * 64 * LDA;         // [2][128*LDA]

    int tid = threadIdx.x;
    int wid = tid >> 5, lane = tid & 31;
    int n0 = ntile * 128;
    int wm = (wid & 3) * 16;
    int wn = (wid >> 2) * 64;
    int c0 = z * nch;

    float acc[8][4];
    #pragma unroll
    for (int b = 0; b < 8; b++)
        #pragma unroll
        for (int q = 0; q < 4; q++) acc[b][q] = 0.f;

    int lrow = tid >> 2;
    int lseg = (tid & 3) * 8;
    const __nv_bfloat16* Ag  = A + (size_t)lrow * kst + c0 * 32 + lseg;
    const __nv_bfloat16* Bg0 = W + (size_t)(n0 + lrow)      * kst + c0 * 32 + lseg;
    const __nv_bfloat16* Bg1 = W + (size_t)(n0 + lrow + 64) * kst + c0 * 32 + lseg;
    int srA = lrow * LDA + lseg;
    int sr1 = (lrow + 64) * LDA + lseg;

    float4 ra  = *(const float4*)Ag;
    float4 rb0 = *(const float4*)Bg0;
    float4 rb1 = *(const float4*)Bg1;

    for (int c = 0; c < nch; c++) {
        int cur = c & 1;
        *(float4*)&sA[cur * 64 * LDA + srA]  = ra;
        *(float4*)&sB[cur * 128 * LDA + srA] = rb0;
        *(float4*)&sB[cur * 128 * LDA + sr1] = rb1;
        if (c + 1 < nch) {
            ra  = *(const float4*)(Ag  + (c + 1) * 32);
            rb0 = *(const float4*)(Bg0 + (c + 1) * 32);
            rb1 = *(const float4*)(Bg1 + (c + 1) * 32);
        }
        __syncthreads();

        #pragma unroll
        for (int ks = 0; ks < 2; ks++) {
            int kc = ks * 16;
            uint32_t afr[4];
            {
                int row = wm + (lane & 15);
                int col = kc + (lane >> 4) * 8;
                uint32_t addr = smem_u32(&sA[cur * 64 * LDA + row * LDA + col]);
                asm volatile("ldmatrix.sync.aligned.m8n8.x4.shared.b16 {%0,%1,%2,%3}, [%4];"
                    : "=r"(afr[0]), "=r"(afr[1]), "=r"(afr[2]), "=r"(afr[3]) : "r"(addr));
            }
            uint32_t bfr[4][4];
            #pragma unroll
            for (int bn = 0; bn < 4; bn++) {
                int sub = lane >> 3;
                int row = wn + bn * 16 + (sub >> 1) * 8 + (lane & 7);
                int col = kc + (sub & 1) * 8;
                uint32_t addr = smem_u32(&sB[cur * 128 * LDA + row * LDA + col]);
                asm volatile("ldmatrix.sync.aligned.m8n8.x4.shared.b16 {%0,%1,%2,%3}, [%4];"
                    : "=r"(bfr[bn][0]), "=r"(bfr[bn][1]), "=r"(bfr[bn][2]), "=r"(bfr[bn][3])
                    : "r"(addr));
            }
            #pragma unroll
            for (int bn = 0; bn < 8; bn++) {
                uint32_t b0 = bfr[bn >> 1][(bn & 1) * 2];
                uint32_t b1 = bfr[bn >> 1][(bn & 1) * 2 + 1];
                asm volatile(
                    "mma.sync.aligned.m16n8k16.row.col.f32.bf16.bf16.f32 "
                    "{%0,%1,%2,%3}, {%4,%5,%6,%7}, {%8,%9}, {%0,%1,%2,%3};"
                    : "+f"(acc[bn][0]), "+f"(acc[bn][1]), "+f"(acc[bn][2]), "+f"(acc[bn][3])
                    : "r"(afr[0]), "r"(afr[1]), "r"(afr[2]), "r"(afr[3]), "r"(b0), "r"(b1));
            }
        }
        __syncthreads();
    }

    int group = lane >> 2, tq = (lane & 3) * 2;
    float* Co = Cp + (size_t)z * 64 * Ntot;
    #pragma unroll
    for (int bn = 0; bn < 8; bn++) {
        int r0 = wm + group;
        int cx = n0 + wn + bn * 8 + tq;
        float2 v0 = { acc[bn][0], acc[bn][1] };
        float2 v1 = { acc[bn][2], acc[bn][3] };
        *(float2*)&Co[(size_t)r0 * Ntot + cx]       = v0;
        *(float2*)&Co[(size_t)(r0 + 8) * Ntot + cx] = v1;
    }
}

// sum rnn_in partials (+relu) -> split into g_GA[0] x-slots
__device__ void ph_comb(int bid) {
    const float* p = (const float*)g_rp;
    for (int k = 0; k < 2; k++) {
        int i = bid * 256 + threadIdx.x + k * 16384;   // BB*EE = 32768, 64 blocks
        int b = i >> 9, col = i & 511;
        float s = 0.f;
        #pragma unroll
        for (int q = 0; q < ZR; q++) s += p[(size_t)q * BB * EE + i];
        s = fmaxf(s, 0.0f);
        __nv_bfloat16 hi, lo;
        bsplit(s, hi, lo);
        g_GA[0][b][col] = hi; g_GA[0][b][1024 + col] = hi; g_GA[0][b][2048 + col] = lo;
    }
}

// LSTM cell layer l at step t
__device__ void ph_cell(int bid, int l, int t, const float* __restrict__ bi,
                        const float* __restrict__ bh) {
    for (int k = 0; k < 2; k++) {
        int idx = bid * 256 + threadIdx.x + k * 16384;  // BB*HH, 64 blocks
        int b = idx >> 9, h = idx & 511;
        float gi = 0.f, gf = 0.f, gg = 0.f, go = 0.f;
        #pragma unroll
        for (int s = 0; s < ZG; s++) {
            gi += g_gp[s][b][h];
            gf += g_gp[s][b][512 + h];
            gg += g_gp[s][b][1024 + h];
            go += g_gp[s][b][1536 + h];
        }
        const float* bip = bi + (size_t)l * 4 * HH;
        const float* bhp = bh + (size_t)l * 4 * HH;
        gi += bip[h]        + bhp[h];
        gf += bip[512 + h]  + bhp[512 + h];
        gg += bip[1024 + h] + bhp[1024 + h];
        go += bip[1536 + h] + bhp[1536 + h];

        float c  = g_c[l][b][h];
        float cn = sigf(gf) * c + sigf(gi) * tanhf(gg);
        float hn = sigf(go) * tanhf(cn);
        g_c[l][b][h] = cn;
        g_h[l][b][h] = hn;

        __nv_bfloat16 hi, lo;
        bsplit(hn, hi, lo);
        if (l == 0) {
            // x-input of layer 1 (this step) + h-input of layer 0 (next step)
            g_GA[1][b][h] = hi; g_GA[1][b][1024 + h] = hi; g_GA[1][b][2048 + h] = lo;
            g_GA[0][b][512 + h] = hi; g_GA[0][b][1536 + h] = hi; g_GA[0][b][2560 + h] = lo;
        } else {
            g_GA[1][b][512 + h] = hi; g_GA[1][b][1536 + h] = hi; g_GA[1][b][2560 + h] = lo;
            __nv_bfloat16* d = &g_Ap[(size_t)(t * BB + b) * KP];
            d[h] = hi; d[512 + h] = hi; d[1024 + h] = lo;
        }
    }
}

// ================= vocab tile (proven 8-warp 128x128 K=1536 GEMM) =================
__device__ void vocab_tile(int m0, int n0, const float* __restrict__ gen_b,
                           float* __restrict__ out, char* smraw)
{
    __nv_bfloat16* sA = (__nv_bfloat16*)smraw;      // [2][128*LDA]
    __nv_bfloat16* sB = sA + 2 * 128 * LDA;         // [2][128*LDA]

    int tid = threadIdx.x;
    int wid = tid >> 5, lane = tid & 31;
    int wm = (wid & 3) * 32;
    int wn = (wid >> 2) * 64;

    float acc[2][8][4];
    #pragma unroll
    for (int a = 0; a < 2; a++)
        #pragma unroll
        for (int b = 0; b < 8; b++)
            #pragma unroll
            for (int q = 0; q < 4; q++) acc[a][b][q] = 0.f;

    int lrow = tid >> 2;
    int lseg = (tid & 3) * 8;
    const __nv_bfloat16* Ag0 = g_Ap + (size_t)(m0 + lrow)      * KP + lseg;
    const __nv_bfloat16* Ag1 = g_Ap + (size_t)(m0 + lrow + 64) * KP + lseg;
    const __nv_bfloat16* Bg0 = g_Wp + (size_t)(n0 + lrow)      * KP + lseg;
    const __nv_bfloat16* Bg1 = g_Wp + (size_t)(n0 + lrow + 64) * KP + lseg;
    int sr0 = lrow * LDA + lseg;
    int sr1 = (lrow + 64) * LDA + lseg;

    float4 ra0 = *(const float4*)Ag0;
    float4 ra1 = *(const float4*)Ag1;
    float4 rb0 = *(const float4*)Bg0;
    float4 rb1 = *(const float4*)Bg1;

    const int NCH = KP / 32;   // 48
    for (int c = 0; c < NCH; c++) {
        int cur = c & 1;
        *(float4*)&sA[cur * 128 * LDA + sr0] = ra0;
        *(float4*)&sA[cur * 128 * LDA + sr1] = ra1;
        *(float4*)&sB[cur * 128 * LDA + sr0] = rb0;
        *(float4*)&sB[cur * 128 * LDA + sr1] = rb1;
        if (c + 1 < NCH) {
            ra0 = *(const float4*)(Ag0 + (c + 1) * 32);
            ra1 = *(const float4*)(Ag1 + (c + 1) * 32);
            rb0 = *(const float4*)(Bg0 + (c + 1) * 32);
            rb1 = *(const float4*)(Bg1 + (c + 1) * 32);
        }
        __syncthreads();

        #pragma unroll
        for (int ks = 0; ks < 2; ks++) {
            int kc = ks * 16;
            uint32_t afr[2][4];
            #pragma unroll
            for (int am = 0; am < 2; am++) {
                int row = wm + am * 16 + (lane & 15);
                int col = kc + (lane >> 4) * 8;
                uint32_t addr = smem_u32(&sA[cur * 128 * LDA + row * LDA + col]);
                asm volatile("ldmatrix.sync.aligned.m8n8.x4.shared.b16 {%0,%1,%2,%3}, [%4];"
                    : "=r"(afr[am][0]), "=r"(afr[am][1]), "=r"(afr[am][2]), "=r"(afr[am][3])
                    : "r"(addr));
            }
            uint32_t bfr[4][4];
            #pragma unroll
            for (int bn = 0; bn < 4; bn++) {
                int sub = lane >> 3;
                int row = wn + bn * 16 + (sub >> 1) * 8 + (lane & 7);
                int col = kc + (sub & 1) * 8;
                uint32_t addr = smem_u32(&sB[cur * 128 * LDA + row * LDA + col]);
                asm volatile("ldmatrix.sync.aligned.m8n8.x4.shared.b16 {%0,%1,%2,%3}, [%4];"
                    : "=r"(bfr[bn][0]), "=r"(bfr[bn][1]), "=r"(bfr[bn][2]), "=r"(bfr[bn][3])
                    : "r"(addr));
            }
            #pragma unroll
            for (int am = 0; am < 2; am++) {
                #pragma unroll
                for (int bn = 0; bn < 8; bn++) {
                    uint32_t b0 = bfr[bn >> 1][(bn & 1) * 2];
                    uint32_t b1 = bfr[bn >> 1][(bn & 1) * 2 + 1];
                    asm volatile(
                        "mma.sync.aligned.m16n8k16.row.col.f32.bf16.bf16.f32 "
                        "{%0,%1,%2,%3}, {%4,%5,%6,%7}, {%8,%9}, {%0,%1,%2,%3};"
                        : "+f"(acc[am][bn][0]), "+f"(acc[am][bn][1]),
                          "+f"(acc[am][bn][2]), "+f"(acc[am][bn][3])
                        : "r"(afr[am][0]), "r"(afr[am][1]), "r"(afr[am][2]), "r"(afr[am][3]),
                          "r"(b0), "r"(b1));
                }
            }
        }
        __syncthreads();
    }

    int group = lane >> 2, tq = (lane & 3) * 2;
    #pragma unroll
    for (int am = 0; am < 2; am++) {
        #pragma unroll
        for (int bn = 0; bn < 8; bn++) {
            int r0 = m0 + wm + am * 16 + group;
            int cx = n0 + wn + bn * 8 + tq;
            float b0 = gen_b[cx], b1 = gen_b[cx + 1];
            float2 v0 = { acc[am][bn][0] + b0, acc[am][bn][1] + b1 };
            float2 v1 = { acc[am][bn][2] + b0, acc[am][bn][3] + b1 };
            *(float2*)&out[(size_t)r0 * VV + cx]       = v0;
            *(float2*)&out[(size_t)(r0 + 8) * VV + cx] = v1;
        }
    }
}

// ================= the persistent kernel =================
__global__ void __launch_bounds__(256) k_rec(
    const int* __restrict__ cur, const int* __restrict__ gtr,
    const float* __restrict__ emb, const float* __restrict__ attn_W,
    const float* __restrict__ enc, const float* __restrict__ bi,
    const float* __restrict__ bh,
    const float* __restrict__ gen_b, float* __restrict__ out)
{
    __shared__ __align__(16) char smraw[4 * 128 * LDA * 2]; // 40960 B (union of uses)
    __shared__ int sv;
    int bid = blockIdx.x, tid = threadIdx.x;

    if (bid < NREC) {
        for (int t = 0; t < TT; t++) {
            const int* tok = (t == 0) ? cur : (gtr + (size_t)(t - 1) * BB);
            // P1: attention, one block per batch element
            ph_attn(bid, tok, emb, attn_W, enc, (float*)smraw, (float*)smraw + 2 * EE);
            gridbar();
            // P2: rnn_in (4 ntiles x 16 z, 6 chunks)
            ph_rgemm(&g_A1[0][0], &g_AOW[0][0], EE, &g_rp[0][0][0],
                     bid & 3, bid >> 2, 6, KR, smraw);
            gridbar();
            ph_comb(bid);
            gridbar();
            // P4: gates l0 (16 ntiles x 4 z, 24 chunks)
            ph_rgemm(&g_GA[0][0][0], &g_GW[0][0][0], 4 * HH, &g_gp[0][0][0],
                     bid & 15, bid >> 4, 24, KR, smraw);
            gridbar();
            ph_cell(bid, 0, t, bi, bh);
            gridbar();
            // P6: gates l1
            ph_rgemm(&g_GA[1][0][0], &g_GW[1][0][0], 4 * HH, &g_gp[0][0][0],
                     bid & 15, bid >> 4, 24, KR, smraw);
            gridbar();
            ph_cell(bid, 1, t, bi, bh);
            gridbar();
            if (bid == 0 && tid == 0) {
                __threadfence();
                g_done = t + 1;        // unlock this step's vocab rows
            }
        }
    }

    // workers (bid >= NREC) immediately; rec blocks join after the recurrence
    for (;;) {
        if (tid == 0) sv = (int)atomicAdd(&g_vtile, 1u);
        __syncthreads();
        int v = sv;
        __syncthreads();
        if (v >= NT_TOT) break;
        int mt = v / NTILE_N;
        int nt = v - mt * NTILE_N;
        if (tid == 0) {
            unsigned need = (unsigned)(2 * mt + 2);
            while (g_done < need) __nanosleep(128);
        }
        __syncthreads();
        vocab_tile(mt * 128, nt * 128, gen_b, out, smraw);
    }
}

// ---------------- one-time weight splits ----------------
__global__ void __launch_bounds__(256) k_cvtW(const float* __restrict__ W) {
    size_t t = (size_t)blockIdx.x * 256 + threadIdx.x;   // VV*512/4
    size_t row = t >> 7;
    int kq = (int)(t & 127) * 4;
    float4 v = *(const float4*)(W + row * 512 + kq);
    __nv_bfloat16 h0, l0, h1, l1, h2, l2, h3, l3;
    bsplit(v.x, h0, l0); bsplit(v.y, h1, l1); bsplit(v.z, h2, l2); bsplit(v.w, h3, l3);
    __nv_bfloat16* d = &g_Wp[row * KP + kq];
    *(__nv_bfloat162*)(d)        = __nv_bfloat162(h0, h1);
    *(__nv_bfloat162*)(d + 2)    = __nv_bfloat162(h2, h3);
    *(__nv_bfloat162*)(d + 512)  = __nv_bfloat162(l0, l1);
    *(__nv_bfloat162*)(d + 514)  = __nv_bfloat162(l2, l3);
    *(__nv_bfloat162*)(d + 1024) = __nv_bfloat162(h0, h1);
    *(__nv_bfloat162*)(d + 1026) = __nv_bfloat162(h2, h3);
}

// [Wi_l | Wh_l] rows over K=1024 -> [hi(1024)|lo(1024)|hi(1024)]
__global__ void __launch_bounds__(256) k_cvtGW(const float* __restrict__ Wi,
                                               const float* __restrict__ Wh) {
    size_t t = (size_t)blockIdx.x * 256 + threadIdx.x;   // NL*2048*1024/4
    if (t >= (size_t)NL * 4 * HH * 1024 / 4) return;
    size_t e = t * 4;
    int l = (int)(e >> 21);
    size_t r = e & ((1u << 21) - 1);
    int n = (int)(r >> 10);
    int k = (int)(r & 1023);
    float4 v;
    if (k < 512) v = *(const float4*)(Wi + ((size_t)l * 4 * HH + n) * 512 + k);
    else         v = *(const float4*)(Wh + ((size_t)l * 4 * HH + n) * 512 + (k - 512));
    __nv_bfloat16 h0, l0, h1, l1, h2, l2, h3, l3;
    bsplit(v.x, h0, l0); bsplit(v.y, h1, l1); bsplit(v.z, h2, l2); bsplit(v.w, h3, l3);
    __nv_bfloat16* d = &g_GW[l][n][k];
    *(__nv_bfloat162*)(d)        = __nv_bfloat162(h0, h1);
    *(__nv_bfloat162*)(d + 2)    = __nv_bfloat162(h2, h3);
    *(__nv_bfloat162*)(d + 1024) = __nv_bfloat162(l0, l1);
    *(__nv_bfloat162*)(d + 1026) = __nv_bfloat162(l2, l3);
    *(__nv_bfloat162*)(d + 2048) = __nv_bfloat162(h0, h1);
    *(__nv_bfloat162*)(d + 2050) = __nv_bfloat162(h2, h3);
}

__global__ void __launch_bounds__(256) k_cvtAOW(const float* __restrict__ W) {
    size_t t = (size_t)blockIdx.x * 256 + threadIdx.x;
    if (t >= (size_t)EE * 1024 / 4) return;
    int row = (int)(t >> 8);
    int k = (int)(t & 255) * 4;
    float4 v = *(const float4*)(W + (size_t)row * 1024 + k);
    __nv_bfloat16 h0, l0, h1, l1, h2, l2, h3, l3;
    bsplit(v.x, h0, l0); bsplit(v.y, h1, l1); bsplit(v.z, h2, l2); bsplit(v.w, h3, l3);
    __nv_bfloat16* d = &g_AOW[row][k];
    *(__nv_bfloat162*)(d)        = __nv_bfloat162(h0, h1);
    *(__nv_bfloat162*)(d + 2)    = __nv_bfloat162(h2, h3);
    *(__nv_bfloat162*)(d + 1024) = __nv_bfloat162(l0, l1);
    *(__nv_bfloat162*)(d + 1026) = __nv_bfloat162(l2, l3);
    *(__nv_bfloat162*)(d + 2048) = __nv_bfloat162(h0, h1);
    *(__nv_bfloat162*)(d + 2050) = __nv_bfloat162(h2, h3);
}

// ---------------- final state copy ----------------
__global__ void k_fin(float* __restrict__ out) {
    int i = blockIdx.x * 256 + threadIdx.x;
    int n = NL * BB * HH;
    if (i < n)           out[i] = ((const float*)g_h)[i];
    else if (i < 2 * n)  out[i] = ((const float*)g_c)[i - n];
}

// ---------------- launch ----------------
extern "C" void kernel_launch(void* const* d_in, const int* in_sizes, int n_in,
                              void* d_out, int out_size) {
    int o = (n_in >= 15) ? 1 : 0;   // optional scalar 'length'
    const int*   cur        = (const int*)  d_in[0];
    const float* h0         = (const float*)d_in[1];
    const float* c0         = (const float*)d_in[2];
    const float* enc        = (const float*)d_in[3];
    const int*   gtr        = (const int*)  d_in[4];
    const float* emb        = (const float*)d_in[5 + o];
    const float* attn_W     = (const float*)d_in[6 + o];
    const float* attn_out_W = (const float*)d_in[7 + o];
    const float* Wi         = (const float*)d_in[8 + o];
    const float* Wh         = (const float*)d_in[9 + o];
    const float* bi         = (const float*)d_in[10 + o];
    const float* bh         = (const float*)d_in[11 + o];
    const float* gen_W      = (const float*)d_in[12 + o];
    const float* gen_b      = (const float*)d_in[13 + o];
    float* out = (float*)d_out;

    k_init<<<(NL * BB * HH + 255) / 256, 256>>>(h0, c0);
    k_cvtW<<<(VV * 512 / 4 + 255) / 256, 256>>>(gen_W);
    k_cvtGW<<<((NL * 4 * HH * 1024 / 4) + 255) / 256, 256>>>(Wi, Wh);
    k_cvtAOW<<<((EE * 1024 / 4) + 255) / 256, 256>>>(attn_out_W);

    // 64 recurrence blocks + 84 vocab workers, one block per SM (148 total)
    k_rec<<<NGRID, 256>>>(cur, gtr, emb, attn_W, enc, bi, bh, gen_b, out);

    size_t sn = (size_t)TT * BB * VV;
    if ((size_t)out_size >= sn + (size_t)2 * NL * BB * HH)
        k_fin<<<(2 * NL * BB * HH + 255) / 256, 256>>>(out + sn);
}

// round 15
// speedup vs baseline: 1.2816x; 1.2816x over previous
#include <cuda_runtime.h>
#include <cuda_bf16.h>
#include <math.h>
#include <stdint.h>

// ---------------- problem constants ----------------
#define TT  32      // timesteps
#define BB  64      // batch
#define HH  512     // hidden
#define EE  512     // embed
#define MLL 64      // encoder length
#define VV  32000   // vocab
#define NL  2       // lstm layers
#define KP  1536    // vocab split-bf16 K (3 x 512)
#define KR  3072    // cat2 split-bf16 K (3 x 1024)
#define KG  1536    // gate-half split-bf16 K (3 x 512)
#define LDA 40      // padded smem row (bf16 units)
#define NBLK 128    // persistent-kernel grid (co-resident)
#define ZR  32      // rnn_in K-split planes
#define ZG  8       // gate x-part K-split planes
#define ZH  2       // gate h-part K-split planes

// ---------------- persistent device state ----------------
__device__ float g_h[NL][BB][HH];
__device__ float g_c[NL][BB][HH];
__device__ float g_rp[ZR][BB][EE];            // rnn_in K-split partials
__device__ float g_gp[ZG][BB][4 * HH];        // gate x-part partials
__device__ float g_gh[NL][ZH][BB][4 * HH];    // gate h-part partials
__device__ __nv_bfloat16 g_A1[BB][KR];        // cat2 split [emb|ctx]
__device__ __nv_bfloat16 g_GAx[NL][BB][KG];   // gate x-input split per layer
__device__ __nv_bfloat16 g_GAh[NL][BB][KG];   // gate h-input split per layer
__device__ __nv_bfloat16 g_AOW[EE][KR];       // attn_out_W split
__device__ __nv_bfloat16 g_GWx[NL][4 * HH][KG];  // Wi_l split
__device__ __nv_bfloat16 g_GWh[NL][4 * HH][KG];  // Wh_l split
__device__ __nv_bfloat16 g_Ap[(size_t)TT * BB * KP];   // vocab A'
__device__ __nv_bfloat16 g_Wp[(size_t)VV * KP];        // vocab W'

// flag-tree grid barrier state (reset by k_init each replay)
__device__ volatile unsigned g_flags[NBLK];
__device__ volatile unsigned g_barg;

__device__ __forceinline__ float sigf(float x) { return 1.0f / (1.0f + expf(-x)); }

__device__ __forceinline__ uint32_t smem_u32(const void* p) {
    uint32_t a;
    asm("{ .reg .u64 t; cvta.to.shared.u64 t, %1; cvt.u32.u64 %0, t; }" : "=r"(a) : "l"(p));
    return a;
}

__device__ __forceinline__ void bsplit(float v, __nv_bfloat16& hi, __nv_bfloat16& lo) {
    hi = __float2bfloat16_rn(v);
    lo = __float2bfloat16_rn(v - __bfloat162float(hi));
}

// flag-tree grid barrier: parallel arrive stores, block 0 polls all flags with
// 128 threads, publishes generation; others spin on the published word.
__device__ __forceinline__ void gridbar(unsigned gen, int bid) {
    __syncthreads();
    if (threadIdx.x == 0) {
        __threadfence();                 // release all prior writes
        g_flags[bid] = gen;              // parallel arrival (distinct addresses)
    }
    if (bid == 0) {
        if (threadIdx.x < NBLK) {
            while (g_flags[threadIdx.x] < gen) {}
            __threadfence();             // acquire
        }
        __syncthreads();
        if (threadIdx.x == 0) g_barg = gen;   // publish (post-fence)
        __syncthreads();
    } else {
        if (threadIdx.x == 0) {
            while (g_barg < gen) {}
            __threadfence();             // acquire
        }
        __syncthreads();
    }
}

// ---------------- init: state copy + h split + barrier reset ----------------
__global__ void k_init(const float* __restrict__ h0, const float* __restrict__ c0) {
    int i = blockIdx.x * 256 + threadIdx.x;
    if (i < NBLK) g_flags[i] = 0;
    if (i == 0) g_barg = 0;
    if (i < NL * BB * HH) {
        ((float*)g_h)[i] = h0[i];
        ((float*)g_c)[i] = c0[i];
        int l = i >> 15, r = i & 32767;
        int b = r >> 9, h = r & 511;
        __nv_bfloat16 hi, lo;
        bsplit(h0[i], hi, lo);
        g_GAh[l][b][h] = hi; g_GAh[l][b][512 + h] = hi; g_GAh[l][b][1024 + h] = lo;
    }
}

// ================= persistent-kernel phases =================

__device__ void ph_attn(int b, const int* __restrict__ tok,
                        const float* __restrict__ emb,
                        const float* __restrict__ attn_W,
                        const float* __restrict__ enc,
                        float* av, float* sc)
{
    int tid = threadIdx.x;
    int t = tok[b];
    const float* er = emb + (size_t)t * EE;
    for (int i = tid; i < EE; i += 256) {
        float v = er[i];
        av[i] = v;
        __nv_bfloat16 hi, lo;
        bsplit(v, hi, lo);
        g_A1[b][i] = hi; g_A1[b][1024 + i] = hi; g_A1[b][2048 + i] = lo;
    }
    const float* hr = &g_h[NL - 1][b][0];
    for (int i = tid; i < HH; i += 256) av[EE + i] = hr[i];
    __syncthreads();

    int w = tid >> 5, lane = tid & 31;
    for (int m = w; m < MLL; m += 8) {
        const float* wr = attn_W + (size_t)m * (EE + HH);
        float s = 0.f;
        #pragma unroll 8
        for (int k = lane; k < EE + HH; k += 32) s = fmaf(av[k], wr[k], s);
        #pragma unroll
        for (int o = 16; o; o >>= 1) s += __shfl_xor_sync(0xffffffffu, s, o);
        if (lane == 0) sc[m] = s;
    }
    __syncthreads();

    if (tid < 32) {
        float a0 = sc[tid], a1 = sc[tid + 32];
        float m = fmaxf(a0, a1);
        #pragma unroll
        for (int o = 16; o; o >>= 1) m = fmaxf(m, __shfl_xor_sync(0xffffffffu, m, o));
        float e0 = expf(a0 - m), e1 = expf(a1 - m);
        float s = e0 + e1;
        #pragma unroll
        for (int o = 16; o; o >>= 1) s += __shfl_xor_sync(0xffffffffu, s, o);
        float inv = 1.0f / s;
        sc[tid] = e0 * inv;
        sc[tid + 32] = e1 * inv;
    }
    __syncthreads();

    for (int h = tid; h < HH; h += 256) {
        float acc = 0.f;
        #pragma unroll 8
        for (int m = 0; m < MLL; m++)
            acc = fmaf(sc[m], enc[((size_t)m * BB + b) * HH + h], acc);
        __nv_bfloat16 hi, lo;
        bsplit(acc, hi, lo);
        g_A1[b][512 + h] = hi; g_A1[b][1536 + h] = hi; g_A1[b][2560 + h] = lo;
    }
    __syncthreads();
}

// K-split GEMM slice: Cp[z][64][Ntot] = A'[64, kst] @ W'[Ntot, kst]^T (ntile cols)
__device__ void ph_rgemm(const __nv_bfloat16* __restrict__ A,
                         const __nv_bfloat16* __restrict__ W,
                         int Ntot, float* __restrict__ Cp,
                         int ntile, int z, int nch, int kst, char* smraw)
{
    __nv_bfloat16* sA = (__nv_bfloat16*)smraw;     // [2][64*LDA]
    __nv_bfloat16* sB = sA + 2 * 64 * LDA;         // [2][128*LDA]

    int tid = threadIdx.x;
    int wid = tid >> 5, lane = tid & 31;
    int n0 = ntile * 128;
    int wm = (wid & 3) * 16;
    int wn = (wid >> 2) * 64;
    int c0 = z * nch;

    float acc[8][4];
    #pragma unroll
    for (int b = 0; b < 8; b++)
        #pragma unroll
        for (int q = 0; q < 4; q++) acc[b][q] = 0.f;

    int lrow = tid >> 2;
    int lseg = (tid & 3) * 8;
    const __nv_bfloat16* Ag  = A + (size_t)lrow * kst + c0 * 32 + lseg;
    const __nv_bfloat16* Bg0 = W + (size_t)(n0 + lrow)      * kst + c0 * 32 + lseg;
    const __nv_bfloat16* Bg1 = W + (size_t)(n0 + lrow + 64) * kst + c0 * 32 + lseg;
    int srA = lrow * LDA + lseg;
    int sr1 = (lrow + 64) * LDA + lseg;

    float4 ra  = *(const float4*)Ag;
    float4 rb0 = *(const float4*)Bg0;
    float4 rb1 = *(const float4*)Bg1;

    for (int c = 0; c < nch; c++) {
        int cur = c & 1;
        *(float4*)&sA[cur * 64 * LDA + srA]  = ra;
        *(float4*)&sB[cur * 128 * LDA + srA] = rb0;
        *(float4*)&sB[cur * 128 * LDA + sr1] = rb1;
        if (c + 1 < nch) {
            ra  = *(const float4*)(Ag  + (c + 1) * 32);
            rb0 = *(const float4*)(Bg0 + (c + 1) * 32);
            rb1 = *(const float4*)(Bg1 + (c + 1) * 32);
        }
        __syncthreads();

        #pragma unroll
        for (int ks = 0; ks < 2; ks++) {
            int kc = ks * 16;
            uint32_t afr[4];
            {
                int row = wm + (lane & 15);
                int col = kc + (lane >> 4) * 8;
                uint32_t addr = smem_u32(&sA[cur * 64 * LDA + row * LDA + col]);
                asm volatile("ldmatrix.sync.aligned.m8n8.x4.shared.b16 {%0,%1,%2,%3}, [%4];"
                    : "=r"(afr[0]), "=r"(afr[1]), "=r"(afr[2]), "=r"(afr[3]) : "r"(addr));
            }
            uint32_t bfr[4][4];
            #pragma unroll
            for (int bn = 0; bn < 4; bn++) {
                int sub = lane >> 3;
                int row = wn + bn * 16 + (sub >> 1) * 8 + (lane & 7);
                int col = kc + (sub & 1) * 8;
                uint32_t addr = smem_u32(&sB[cur * 128 * LDA + row * LDA + col]);
                asm volatile("ldmatrix.sync.aligned.m8n8.x4.shared.b16 {%0,%1,%2,%3}, [%4];"
                    : "=r"(bfr[bn][0]), "=r"(bfr[bn][1]), "=r"(bfr[bn][2]), "=r"(bfr[bn][3])
                    : "r"(addr));
            }
            #pragma unroll
            for (int bn = 0; bn < 8; bn++) {
                uint32_t b0 = bfr[bn >> 1][(bn & 1) * 2];
                uint32_t b1 = bfr[bn >> 1][(bn & 1) * 2 + 1];
                asm volatile(
                    "mma.sync.aligned.m16n8k16.row.col.f32.bf16.bf16.f32 "
                    "{%0,%1,%2,%3}, {%4,%5,%6,%7}, {%8,%9}, {%0,%1,%2,%3};"
                    : "+f"(acc[bn][0]), "+f"(acc[bn][1]), "+f"(acc[bn][2]), "+f"(acc[bn][3])
                    : "r"(afr[0]), "r"(afr[1]), "r"(afr[2]), "r"(afr[3]), "r"(b0), "r"(b1));
            }
        }
        __syncthreads();
    }

    int group = lane >> 2, tq = (lane & 3) * 2;
    float* Co = Cp + (size_t)z * 64 * Ntot;
    #pragma unroll
    for (int bn = 0; bn < 8; bn++) {
        int r0 = wm + group;
        int cx = n0 + wn + bn * 8 + tq;
        float2 v0 = { acc[bn][0], acc[bn][1] };
        float2 v1 = { acc[bn][2], acc[bn][3] };
        *(float2*)&Co[(size_t)r0 * Ntot + cx]       = v0;
        *(float2*)&Co[(size_t)(r0 + 8) * Ntot + cx] = v1;
    }
}

// sum rnn_in partials (+relu) -> split into g_GAx[0]
__device__ void ph_comb() {
    int i = blockIdx.x * 256 + threadIdx.x;   // BB*EE = 32768
    int b = i >> 9, col = i & 511;
    const float* p = (const float*)g_rp;
    float s = 0.f;
    #pragma unroll
    for (int q = 0; q < ZR; q++) s += p[(size_t)q * BB * EE + i];
    s = fmaxf(s, 0.0f);
    __nv_bfloat16 hi, lo;
    bsplit(s, hi, lo);
    g_GAx[0][b][col] = hi; g_GAx[0][b][512 + col] = hi; g_GAx[0][b][1024 + col] = lo;
}

// LSTM cell layer l at step t
__device__ void ph_cell(int l, int t, const float* __restrict__ bi,
                        const float* __restrict__ bh) {
    int idx = blockIdx.x * 256 + threadIdx.x;  // BB*HH
    int b = idx >> 9, h = idx & 511;
    float gi = 0.f, gf = 0.f, gg = 0.f, go = 0.f;
    #pragma unroll
    for (int s = 0; s < ZG; s++) {
        gi += g_gp[s][b][h];
        gf += g_gp[s][b][512 + h];
        gg += g_gp[s][b][1024 + h];
        go += g_gp[s][b][1536 + h];
    }
    #pragma unroll
    for (int s = 0; s < ZH; s++) {
        gi += g_gh[l][s][b][h];
        gf += g_gh[l][s][b][512 + h];
        gg += g_gh[l][s][b][1024 + h];
        go += g_gh[l][s][b][1536 + h];
    }
    const float* bip = bi + (size_t)l * 4 * HH;
    const float* bhp = bh + (size_t)l * 4 * HH;
    gi += bip[h]        + bhp[h];
    gf += bip[512 + h]  + bhp[512 + h];
    gg += bip[1024 + h] + bhp[1024 + h];
    go += bip[1536 + h] + bhp[1536 + h];

    float c  = g_c[l][b][h];
    float cn = sigf(gf) * c + sigf(gi) * tanhf(gg);
    float hn = sigf(go) * tanhf(cn);
    g_c[l][b][h] = cn;
    g_h[l][b][h] = hn;

    __nv_bfloat16 hi, lo;
    bsplit(hn, hi, lo);
    if (l == 0) {
        g_GAx[1][b][h] = hi; g_GAx[1][b][512 + h] = hi; g_GAx[1][b][1024 + h] = lo;
        g_GAh[0][b][h] = hi; g_GAh[0][b][512 + h] = hi; g_GAh[0][b][1024 + h] = lo;
    } else {
        g_GAh[1][b][h] = hi; g_GAh[1][b][512 + h] = hi; g_GAh[1][b][1024 + h] = lo;
        __nv_bfloat16* d = &g_Ap[(size_t)(t * BB + b) * KP];
        d[h] = hi; d[512 + h] = hi; d[1024 + h] = lo;
    }
}

// ---------------- the persistent recurrence kernel ----------------
__global__ void __launch_bounds__(256) k_rec(
    const int* __restrict__ cur, const int* __restrict__ gtr,
    const float* __restrict__ emb, const float* __restrict__ attn_W,
    const float* __restrict__ enc, const float* __restrict__ bi,
    const float* __restrict__ bh)
{
    __shared__ __align__(16) char smraw[(2 * 64 * LDA + 2 * 128 * LDA) * 2]; // 30720 B
    int bid = blockIdx.x;
    unsigned gen = 0;

    for (int t = 0; t < TT; t++) {
        const int* tok = (t == 0) ? cur : (gtr + (size_t)(t - 1) * BB);
        // P1: attention (0-63) || gate h-part GEMMs for both layers (64-127)
        if (bid < 64) {
            ph_attn(bid, tok, emb, attn_W, enc, (float*)smraw, (float*)smraw + 2 * EE);
        } else {
            int q = bid - 64;
            int l = q >> 5, s = q & 31;
            ph_rgemm(&g_GAh[l][0][0], &g_GWh[l][0][0], 4 * HH, &g_gh[l][0][0][0],
                     s & 15, s >> 4, (KG / 32) / ZH, KG, smraw);
        }
        gridbar(++gen, bid);
        // P2: rnn_in GEMM (cat2 @ AOW^T)
        ph_rgemm(&g_A1[0][0], &g_AOW[0][0], EE, &g_rp[0][0][0],
                 bid & 3, bid >> 2, 3, KR, smraw);
        gridbar(++gen, bid);
        // P3: relu + split
        ph_comb();
        gridbar(++gen, bid);
        // P4: gates l0 x-part
        ph_rgemm(&g_GAx[0][0][0], &g_GWx[0][0][0], 4 * HH, &g_gp[0][0][0],
                 bid & 15, bid >> 4, (KG / 32) / ZG, KG, smraw);
        gridbar(++gen, bid);
        ph_cell(0, t, bi, bh);
        gridbar(++gen, bid);
        // P6: gates l1 x-part
        ph_rgemm(&g_GAx[1][0][0], &g_GWx[1][0][0], 4 * HH, &g_gp[0][0][0],
                 bid & 15, bid >> 4, (KG / 32) / ZG, KG, smraw);
        gridbar(++gen, bid);
        ph_cell(1, t, bi, bh);
        gridbar(++gen, bid);
    }
}

// ---------------- one-time weight splits ----------------
__global__ void __launch_bounds__(256) k_cvtW(const float* __restrict__ W) {
    size_t t = (size_t)blockIdx.x * 256 + threadIdx.x;   // VV*512/4
    size_t row = t >> 7;
    int kq = (int)(t & 127) * 4;
    float4 v = *(const float4*)(W + row * 512 + kq);
    __nv_bfloat16 h0, l0, h1, l1, h2, l2, h3, l3;
    bsplit(v.x, h0, l0); bsplit(v.y, h1, l1); bsplit(v.z, h2, l2); bsplit(v.w, h3, l3);
    __nv_bfloat16* d = &g_Wp[row * KP + kq];
    *(__nv_bfloat162*)(d)        = __nv_bfloat162(h0, h1);
    *(__nv_bfloat162*)(d + 2)    = __nv_bfloat162(h2, h3);
    *(__nv_bfloat162*)(d + 512)  = __nv_bfloat162(l0, l1);
    *(__nv_bfloat162*)(d + 514)  = __nv_bfloat162(l2, l3);
    *(__nv_bfloat162*)(d + 1024) = __nv_bfloat162(h0, h1);
    *(__nv_bfloat162*)(d + 1026) = __nv_bfloat162(h2, h3);
}

// Wi -> GWx, Wh -> GWh: per row over K=512 -> [hi(512)|lo(512)|hi(512)]
__global__ void __launch_bounds__(256) k_cvtGW(const float* __restrict__ Wi,
                                               const float* __restrict__ Wh) {
    size_t t = (size_t)blockIdx.x * 256 + threadIdx.x;   // NL*2048*128
    if (t >= (size_t)NL * 4 * HH * 128) return;
    int l = (int)(t >> 18);
    size_t r = t & ((1u << 18) - 1);
    int n = (int)(r >> 7);
    int k = (int)(r & 127) * 4;

    float4 v = *(const float4*)(Wi + ((size_t)l * 4 * HH + n) * 512 + k);
    __nv_bfloat16 h0, l0, h1, l1, h2, l2, h3, l3;
    bsplit(v.x, h0, l0); bsplit(v.y, h1, l1); bsplit(v.z, h2, l2); bsplit(v.w, h3, l3);
    __nv_bfloat16* d = &g_GWx[l][n][k];
    *(__nv_bfloat162*)(d)        = __nv_bfloat162(h0, h1);
    *(__nv_bfloat162*)(d + 2)    = __nv_bfloat162(h2, h3);
    *(__nv_bfloat162*)(d + 512)  = __nv_bfloat162(l0, l1);
    *(__nv_bfloat162*)(d + 514)  = __nv_bfloat162(l2, l3);
    *(__nv_bfloat162*)(d + 1024) = __nv_bfloat162(h0, h1);
    *(__nv_bfloat162*)(d + 1026) = __nv_bfloat162(h2, h3);

    v = *(const float4*)(Wh + ((size_t)l * 4 * HH + n) * 512 + k);
    bsplit(v.x, h0, l0); bsplit(v.y, h1, l1); bsplit(v.z, h2, l2); bsplit(v.w, h3, l3);
    d = &g_GWh[l][n][k];
    *(__nv_bfloat162*)(d)        = __nv_bfloat162(h0, h1);
    *(__nv_bfloat162*)(d + 2)    = __nv_bfloat162(h2, h3);
    *(__nv_bfloat162*)(d + 512)  = __nv_bfloat162(l0, l1);
    *(__nv_bfloat162*)(d + 514)  = __nv_bfloat162(l2, l3);
    *(__nv_bfloat162*)(d + 1024) = __nv_bfloat162(h0, h1);
    *(__nv_bfloat162*)(d + 1026) = __nv_bfloat162(h2, h3);
}

__global__ void __launch_bounds__(256) k_cvtAOW(const float* __restrict__ W) {
    size_t t = (size_t)blockIdx.x * 256 + threadIdx.x;
    if (t >= (size_t)EE * 1024 / 4) return;
    int row = (int)(t >> 8);
    int k = (int)(t & 255) * 4;
    float4 v = *(const float4*)(W + (size_t)row * 1024 + k);
    __nv_bfloat16 h0, l0, h1, l1, h2, l2, h3, l3;
    bsplit(v.x, h0, l0); bsplit(v.y, h1, l1); bsplit(v.z, h2, l2); bsplit(v.w, h3, l3);
    __nv_bfloat16* d = &g_AOW[row][k];
    *(__nv_bfloat162*)(d)        = __nv_bfloat162(h0, h1);
    *(__nv_bfloat162*)(d + 2)    = __nv_bfloat162(h2, h3);
    *(__nv_bfloat162*)(d + 1024) = __nv_bfloat162(l0, l1);
    *(__nv_bfloat162*)(d + 1026) = __nv_bfloat162(l2, l3);
    *(__nv_bfloat162*)(d + 2048) = __nv_bfloat162(h0, h1);
    *(__nv_bfloat162*)(d + 2050) = __nv_bfloat162(h2, h3);
}

// ---------------- vocab GEMM via warp-level mma.sync (bf16 -> fp32) ----------------
#define VBK 32

__global__ void __launch_bounds__(256, 2) k_vocab(const float* __restrict__ gen_b,
                                                  float* __restrict__ out)
{
    __shared__ __nv_bfloat16 sA[2][128 * LDA];
    __shared__ __nv_bfloat16 sB[2][128 * LDA];

    int tid = threadIdx.x;
    int wid = tid >> 5, lane = tid & 31;
    int n0 = blockIdx.x * 128;
    int m0 = blockIdx.y * 128;
    int wm = (wid & 3) * 32;
    int wn = (wid >> 2) * 64;

    float acc[2][8][4];
    #pragma unroll
    for (int a = 0; a < 2; a++)
        #pragma unroll
        for (int b = 0; b < 8; b++)
            #pragma unroll
            for (int q = 0; q < 4; q++) acc[a][b][q] = 0.f;

    int lrow = tid >> 2;
    int lseg = (tid & 3) * 8;
    const __nv_bfloat16* Ag0 = g_Ap + (size_t)(m0 + lrow)      * KP + lseg;
    const __nv_bfloat16* Ag1 = g_Ap + (size_t)(m0 + lrow + 64) * KP + lseg;
    const __nv_bfloat16* Bg0 = g_Wp + (size_t)(n0 + lrow)      * KP + lseg;
    const __nv_bfloat16* Bg1 = g_Wp + (size_t)(n0 + lrow + 64) * KP + lseg;
    int sr0 = lrow * LDA + lseg;
    int sr1 = (lrow + 64) * LDA + lseg;

    float4 ra0 = *(const float4*)Ag0;
    float4 ra1 = *(const float4*)Ag1;
    float4 rb0 = *(const float4*)Bg0;
    float4 rb1 = *(const float4*)Bg1;

    const int NCH = KP / VBK;   // 48
    for (int c = 0; c < NCH; c++) {
        int cur = c & 1;
        *(float4*)&sA[cur][sr0] = ra0;
        *(float4*)&sA[cur][sr1] = ra1;
        *(float4*)&sB[cur][sr0] = rb0;
        *(float4*)&sB[cur][sr1] = rb1;
        if (c + 1 < NCH) {
            ra0 = *(const float4*)(Ag0 + (c + 1) * VBK);
            ra1 = *(const float4*)(Ag1 + (c + 1) * VBK);
            rb0 = *(const float4*)(Bg0 + (c + 1) * VBK);
            rb1 = *(const float4*)(Bg1 + (c + 1) * VBK);
        }
        __syncthreads();

        #pragma unroll
        for (int ks = 0; ks < 2; ks++) {
            int kc = ks * 16;
            uint32_t afr[2][4];
            #pragma unroll
            for (int am = 0; am < 2; am++) {
                int row = wm + am * 16 + (lane & 15);
                int col = kc + (lane >> 4) * 8;
                uint32_t addr = smem_u32(&sA[cur][row * LDA + col]);
                asm volatile("ldmatrix.sync.aligned.m8n8.x4.shared.b16 {%0,%1,%2,%3}, [%4];"
                    : "=r"(afr[am][0]), "=r"(afr[am][1]), "=r"(afr[am][2]), "=r"(afr[am][3])
                    : "r"(addr));
            }
            uint32_t bfr[4][4];
            #pragma unroll
            for (int bn = 0; bn < 4; bn++) {
                int sub = lane >> 3;
                int row = wn + bn * 16 + (sub >> 1) * 8 + (lane & 7);
                int col = kc + (sub & 1) * 8;
                uint32_t addr = smem_u32(&sB[cur][row * LDA + col]);
                asm volatile("ldmatrix.sync.aligned.m8n8.x4.shared.b16 {%0,%1,%2,%3}, [%4];"
                    : "=r"(bfr[bn][0]), "=r"(bfr[bn][1]), "=r"(bfr[bn][2]), "=r"(bfr[bn][3])
                    : "r"(addr));
            }
            #pragma unroll
            for (int am = 0; am < 2; am++) {
                #pragma unroll
                for (int bn = 0; bn < 8; bn++) {
                    uint32_t b0 = bfr[bn >> 1][(bn & 1) * 2];
                    uint32_t b1 = bfr[bn >> 1][(bn & 1) * 2 + 1];
                    asm volatile(
                        "mma.sync.aligned.m16n8k16.row.col.f32.bf16.bf16.f32 "
                        "{%0,%1,%2,%3}, {%4,%5,%6,%7}, {%8,%9}, {%0,%1,%2,%3};"
                        : "+f"(acc[am][bn][0]), "+f"(acc[am][bn][1]),
                          "+f"(acc[am][bn][2]), "+f"(acc[am][bn][3])
                        : "r"(afr[am][0]), "r"(afr[am][1]), "r"(afr[am][2]), "r"(afr[am][3]),
                          "r"(b0), "r"(b1));
                }
            }
        }
    }

    int group = lane >> 2, tq = (lane & 3) * 2;
    #pragma unroll
    for (int am = 0; am < 2; am++) {
        #pragma unroll
        for (int bn = 0; bn < 8; bn++) {
            int r0 = m0 + wm + am * 16 + group;
            int cx = n0 + wn + bn * 8 + tq;
            float b0 = gen_b[cx], b1 = gen_b[cx + 1];
            float2 v0 = { acc[am][bn][0] + b0, acc[am][bn][1] + b1 };
            float2 v1 = { acc[am][bn][2] + b0, acc[am][bn][3] + b1 };
            *(float2*)&out[(size_t)r0 * VV + cx]       = v0;
            *(float2*)&out[(size_t)(r0 + 8) * VV + cx] = v1;
        }
    }
}

// ---------------- final state copy ----------------
__global__ void k_fin(float* __restrict__ out) {
    int i = blockIdx.x * 256 + threadIdx.x;
    int n = NL * BB * HH;
    if (i < n)           out[i] = ((const float*)g_h)[i];
    else if (i < 2 * n)  out[i] = ((const float*)g_c)[i - n];
}

// ---------------- launch ----------------
extern "C" void kernel_launch(void* const* d_in, const int* in_sizes, int n_in,
                              void* d_out, int out_size) {
    int o = (n_in >= 15) ? 1 : 0;   // optional scalar 'length'
    const int*   cur        = (const int*)  d_in[0];
    const float* h0         = (const float*)d_in[1];
    const float* c0         = (const float*)d_in[2];
    const float* enc        = (const float*)d_in[3];
    const int*   gtr        = (const int*)  d_in[4];
    const float* emb        = (const float*)d_in[5 + o];
    const float* attn_W     = (const float*)d_in[6 + o];
    const float* attn_out_W = (const float*)d_in[7 + o];
    const float* Wi         = (const float*)d_in[8 + o];
    const float* Wh         = (const float*)d_in[9 + o];
    const float* bi         = (const float*)d_in[10 + o];
    const float* bh         = (const float*)d_in[11 + o];
    const float* gen_W      = (const float*)d_in[12 + o];
    const float* gen_b      = (const float*)d_in[13 + o];
    float* out = (float*)d_out;

    k_init<<<(NL * BB * HH + 255) / 256, 256>>>(h0, c0);
    k_cvtW<<<(VV * 512 / 4 + 255) / 256, 256>>>(gen_W);
    k_cvtGW<<<((NL * 4 * HH * 128) + 255) / 256, 256>>>(Wi, Wh);
    k_cvtAOW<<<((EE * 1024 / 4) + 255) / 256, 256>>>(attn_out_W);

    // entire 32-step recurrence in one persistent kernel (flag-tree barrier)
    k_rec<<<NBLK, 256>>>(cur, gtr, emb, attn_W, enc, bi, bh);

    // vocab GEMM over all steps' top-layer h
    k_vocab<<<dim3(VV / 128, (TT * BB) / 128), 256>>>(gen_b, out);

    size_t sn = (size_t)TT * BB * VV;
    if ((size_t)out_size >= sn + (size_t)2 * NL * BB * HH)
        k_fin<<<(2 * NL * BB * HH + 255) / 256, 256>>>(out + sn);
}

// round 16
// speedup vs baseline: 1.3362x; 1.0426x over previous
#include <cuda_runtime.h>
#include <cuda_bf16.h>
#include <math.h>
#include <stdint.h>

// ---------------- problem constants ----------------
#define TT  32      // timesteps
#define BB  64      // batch
#define HH  512     // hidden
#define EE  512     // embed
#define MLL 64      // encoder length
#define VV  32000   // vocab
#define NL  2       // lstm layers
#define KP  1536    // vocab split-bf16 K (3 x 512)
#define KR  3072    // cat2 split-bf16 K (3 x 1024)
#define KG  1536    // gate-half split-bf16 K (3 x 512)
#define LDA 40      // padded smem row (bf16 units)
#define NBLK 128    // persistent-kernel grid (co-resident)
#define ZR  32      // rnn_in K-split planes
#define ZG  8       // gate x-part K-split planes
#define ZH  2       // gate h-part K-split planes

// ---------------- persistent device state ----------------
__device__ float g_h[NL][BB][HH];
__device__ float g_c[NL][BB][HH];
__device__ float g_rp[ZR][BB][EE];            // rnn_in K-split partials
__device__ float g_gp[ZG][BB][4 * HH];        // gate x-part partials
__device__ float g_gh[NL][ZH][BB][4 * HH];    // gate h-part partials
__device__ __nv_bfloat16 g_A1[BB][KR];        // cat2 split [emb|ctx]
__device__ __nv_bfloat16 g_GAx[NL][BB][KG];   // gate x-input split per layer
__device__ __nv_bfloat16 g_GAh[NL][BB][KG];   // gate h-input split per layer
__device__ __nv_bfloat16 g_AOW[EE][KR];       // attn_out_W split
__device__ __nv_bfloat16 g_GWx[NL][4 * HH][KG];  // Wi_l split
__device__ __nv_bfloat16 g_GWh[NL][4 * HH][KG];  // Wh_l split
__device__ __nv_bfloat16 g_Ap[(size_t)TT * BB * KP];   // vocab A'
__device__ __nv_bfloat16 g_Wp[(size_t)VV * KP];        // vocab W'

// software grid barrier (zero-init; counter self-resets)
__device__ unsigned g_barc;
__device__ volatile unsigned g_barg;

__device__ __forceinline__ float sigf(float x) { return 1.0f / (1.0f + expf(-x)); }

__device__ __forceinline__ uint32_t smem_u32(const void* p) {
    uint32_t a;
    asm("{ .reg .u64 t; cvta.to.shared.u64 t, %1; cvt.u32.u64 %0, t; }" : "=r"(a) : "l"(p));
    return a;
}

__device__ __forceinline__ void bsplit(float v, __nv_bfloat16& hi, __nv_bfloat16& lo) {
    hi = __float2bfloat16_rn(v);
    lo = __float2bfloat16_rn(v - __bfloat162float(hi));
}

// grid barrier: fence -> arrive -> last flips generation; others hot-spin on L2.
__device__ __forceinline__ void gridbar() {
    __syncthreads();
    if (threadIdx.x == 0) {
        unsigned g = g_barg;
        __threadfence();
        if (atomicAdd(&g_barc, 1u) == NBLK - 1) {
            g_barc = 0;
            __threadfence();
            g_barg = g + 1;
        } else {
            while (g_barg == g) {}
            __threadfence();
        }
    }
    __syncthreads();
}

// cp.async helpers (16B)
#define CP_ASYNC16(dst, src) \
    asm volatile("cp.async.cg.shared.global [%0], [%1], 16;" :: "r"(dst), "l"(src))
#define CP_COMMIT()  asm volatile("cp.async.commit_group;" ::: "memory")
#define CP_WAIT0()   asm volatile("cp.async.wait_group 0;" ::: "memory")

// ---------------- init: state copy + h split into GAh ----------------
__global__ void k_init(const float* __restrict__ h0, const float* __restrict__ c0) {
    int i = blockIdx.x * 256 + threadIdx.x;
    if (i < NL * BB * HH) {
        ((float*)g_h)[i] = h0[i];
        ((float*)g_c)[i] = c0[i];
        int l = i >> 15, r = i & 32767;
        int b = r >> 9, h = r & 511;
        __nv_bfloat16 hi, lo;
        bsplit(h0[i], hi, lo);
        g_GAh[l][b][h] = hi; g_GAh[l][b][512 + h] = hi; g_GAh[l][b][1024 + h] = lo;
    }
}

// ================= persistent-kernel phases =================

__device__ void ph_attn(int b, const int* __restrict__ tok,
                        const float* __restrict__ emb,
                        const float* __restrict__ attn_W,
                        const float* __restrict__ enc,
                        float* av, float* sc)
{
    int tid = threadIdx.x;
    int t = tok[b];
    const float* er = emb + (size_t)t * EE;
    for (int i = tid; i < EE; i += 256) {
        float v = er[i];
        av[i] = v;
        __nv_bfloat16 hi, lo;
        bsplit(v, hi, lo);
        g_A1[b][i] = hi; g_A1[b][1024 + i] = hi; g_A1[b][2048 + i] = lo;
    }
    const float* hr = &g_h[NL - 1][b][0];
    for (int i = tid; i < HH; i += 256) av[EE + i] = hr[i];
    __syncthreads();

    int w = tid >> 5, lane = tid & 31;
    for (int m = w; m < MLL; m += 8) {
        const float* wr = attn_W + (size_t)m * (EE + HH);
        float s = 0.f;
        #pragma unroll 8
        for (int k = lane; k < EE + HH; k += 32) s = fmaf(av[k], wr[k], s);
        #pragma unroll
        for (int o = 16; o; o >>= 1) s += __shfl_xor_sync(0xffffffffu, s, o);
        if (lane == 0) sc[m] = s;
    }
    __syncthreads();

    if (tid < 32) {
        float a0 = sc[tid], a1 = sc[tid + 32];
        float m = fmaxf(a0, a1);
        #pragma unroll
        for (int o = 16; o; o >>= 1) m = fmaxf(m, __shfl_xor_sync(0xffffffffu, m, o));
        float e0 = expf(a0 - m), e1 = expf(a1 - m);
        float s = e0 + e1;
        #pragma unroll
        for (int o = 16; o; o >>= 1) s += __shfl_xor_sync(0xffffffffu, s, o);
        float inv = 1.0f / s;
        sc[tid] = e0 * inv;
        sc[tid + 32] = e1 * inv;
    }
    __syncthreads();

    for (int h = tid; h < HH; h += 256) {
        float acc = 0.f;
        #pragma unroll 8
        for (int m = 0; m < MLL; m++)
            acc = fmaf(sc[m], enc[((size_t)m * BB + b) * HH + h], acc);
        __nv_bfloat16 hi, lo;
        bsplit(acc, hi, lo);
        g_A1[b][512 + h] = hi; g_A1[b][1536 + h] = hi; g_A1[b][2560 + h] = lo;
    }
    __syncthreads();
}

// K-split GEMM slice: Cp[z][64][Ntot] = A'[64, kst] @ W'[Ntot, kst]^T (ntile cols)
__device__ void ph_rgemm(const __nv_bfloat16* __restrict__ A,
                         const __nv_bfloat16* __restrict__ W,
                         int Ntot, float* __restrict__ Cp,
                         int ntile, int z, int nch, int kst, char* smraw)
{
    __nv_bfloat16* sA = (__nv_bfloat16*)smraw;     // [2][64*LDA]
    __nv_bfloat16* sB = sA + 2 * 64 * LDA;         // [2][128*LDA]

    int tid = threadIdx.x;
    int wid = tid >> 5, lane = tid & 31;
    int n0 = ntile * 128;
    int wm = (wid & 3) * 16;
    int wn = (wid >> 2) * 64;
    int c0 = z * nch;

    float acc[8][4];
    #pragma unroll
    for (int b = 0; b < 8; b++)
        #pragma unroll
        for (int q = 0; q < 4; q++) acc[b][q] = 0.f;

    int lrow = tid >> 2;
    int lseg = (tid & 3) * 8;
    const __nv_bfloat16* Ag  = A + (size_t)lrow * kst + c0 * 32 + lseg;
    const __nv_bfloat16* Bg0 = W + (size_t)(n0 + lrow)      * kst + c0 * 32 + lseg;
    const __nv_bfloat16* Bg1 = W + (size_t)(n0 + lrow + 64) * kst + c0 * 32 + lseg;
    int srA = lrow * LDA + lseg;
    int sr1 = (lrow + 64) * LDA + lseg;

    float4 ra  = *(const float4*)Ag;
    float4 rb0 = *(const float4*)Bg0;
    float4 rb1 = *(const float4*)Bg1;

    for (int c = 0; c < nch; c++) {
        int cur = c & 1;
        *(float4*)&sA[cur * 64 * LDA + srA]  = ra;
        *(float4*)&sB[cur * 128 * LDA + srA] = rb0;
        *(float4*)&sB[cur * 128 * LDA + sr1] = rb1;
        if (c + 1 < nch) {
            ra  = *(const float4*)(Ag  + (c + 1) * 32);
            rb0 = *(const float4*)(Bg0 + (c + 1) * 32);
            rb1 = *(const float4*)(Bg1 + (c + 1) * 32);
        }
        __syncthreads();

        #pragma unroll
        for (int ks = 0; ks < 2; ks++) {
            int kc = ks * 16;
            uint32_t afr[4];
            {
                int row = wm + (lane & 15);
                int col = kc + (lane >> 4) * 8;
                uint32_t addr = smem_u32(&sA[cur * 64 * LDA + row * LDA + col]);
                asm volatile("ldmatrix.sync.aligned.m8n8.x4.shared.b16 {%0,%1,%2,%3}, [%4];"
                    : "=r"(afr[0]), "=r"(afr[1]), "=r"(afr[2]), "=r"(afr[3]) : "r"(addr));
            }
            uint32_t bfr[4][4];
            #pragma unroll
            for (int bn = 0; bn < 4; bn++) {
                int sub = lane >> 3;
                int row = wn + bn * 16 + (sub >> 1) * 8 + (lane & 7);
                int col = kc + (sub & 1) * 8;
                uint32_t addr = smem_u32(&sB[cur * 128 * LDA + row * LDA + col]);
                asm volatile("ldmatrix.sync.aligned.m8n8.x4.shared.b16 {%0,%1,%2,%3}, [%4];"
                    : "=r"(bfr[bn][0]), "=r"(bfr[bn][1]), "=r"(bfr[bn][2]), "=r"(bfr[bn][3])
                    : "r"(addr));
            }
            #pragma unroll
            for (int bn = 0; bn < 8; bn++) {
                uint32_t b0 = bfr[bn >> 1][(bn & 1) * 2];
                uint32_t b1 = bfr[bn >> 1][(bn & 1) * 2 + 1];
                asm volatile(
                    "mma.sync.aligned.m16n8k16.row.col.f32.bf16.bf16.f32 "
                    "{%0,%1,%2,%3}, {%4,%5,%6,%7}, {%8,%9}, {%0,%1,%2,%3};"
                    : "+f"(acc[bn][0]), "+f"(acc[bn][1]), "+f"(acc[bn][2]), "+f"(acc[bn][3])
                    : "r"(afr[0]), "r"(afr[1]), "r"(afr[2]), "r"(afr[3]), "r"(b0), "r"(b1));
            }
        }
        __syncthreads();
    }

    int group = lane >> 2, tq = (lane & 3) * 2;
    float* Co = Cp + (size_t)z * 64 * Ntot;
    #pragma unroll
    for (int bn = 0; bn < 8; bn++) {
        int r0 = wm + group;
        int cx = n0 + wn + bn * 8 + tq;
        float2 v0 = { acc[bn][0], acc[bn][1] };
        float2 v1 = { acc[bn][2], acc[bn][3] };
        *(float2*)&Co[(size_t)r0 * Ntot + cx]       = v0;
        *(float2*)&Co[(size_t)(r0 + 8) * Ntot + cx] = v1;
    }
}

// sum rnn_in partials (+relu) -> split into g_GAx[0]
__device__ void ph_comb() {
    int i = blockIdx.x * 256 + threadIdx.x;   // BB*EE = 32768
    int b = i >> 9, col = i & 511;
    const float* p = (const float*)g_rp;
    float s = 0.f;
    #pragma unroll
    for (int q = 0; q < ZR; q++) s += p[(size_t)q * BB * EE + i];
    s = fmaxf(s, 0.0f);
    __nv_bfloat16 hi, lo;
    bsplit(s, hi, lo);
    g_GAx[0][b][col] = hi; g_GAx[0][b][512 + col] = hi; g_GAx[0][b][1024 + col] = lo;
}

// LSTM cell layer l at step t
__device__ void ph_cell(int l, int t, const float* __restrict__ bi,
                        const float* __restrict__ bh) {
    int idx = blockIdx.x * 256 + threadIdx.x;  // BB*HH
    int b = idx >> 9, h = idx & 511;
    float gi = 0.f, gf = 0.f, gg = 0.f, go = 0.f;
    #pragma unroll
    for (int s = 0; s < ZG; s++) {
        gi += g_gp[s][b][h];
        gf += g_gp[s][b][512 + h];
        gg += g_gp[s][b][1024 + h];
        go += g_gp[s][b][1536 + h];
    }
    #pragma unroll
    for (int s = 0; s < ZH; s++) {
        gi += g_gh[l][s][b][h];
        gf += g_gh[l][s][b][512 + h];
        gg += g_gh[l][s][b][1024 + h];
        go += g_gh[l][s][b][1536 + h];
    }
    const float* bip = bi + (size_t)l * 4 * HH;
    const float* bhp = bh + (size_t)l * 4 * HH;
    gi += bip[h]        + bhp[h];
    gf += bip[512 + h]  + bhp[512 + h];
    gg += bip[1024 + h] + bhp[1024 + h];
    go += bip[1536 + h] + bhp[1536 + h];

    float c  = g_c[l][b][h];
    float cn = sigf(gf) * c + sigf(gi) * tanhf(gg);
    float hn = sigf(go) * tanhf(cn);
    g_c[l][b][h] = cn;
    g_h[l][b][h] = hn;

    __nv_bfloat16 hi, lo;
    bsplit(hn, hi, lo);
    if (l == 0) {
        g_GAx[1][b][h] = hi; g_GAx[1][b][512 + h] = hi; g_GAx[1][b][1024 + h] = lo;
        g_GAh[0][b][h] = hi; g_GAh[0][b][512 + h] = hi; g_GAh[0][b][1024 + h] = lo;
    } else {
        g_GAh[1][b][h] = hi; g_GAh[1][b][512 + h] = hi; g_GAh[1][b][1024 + h] = lo;
        __nv_bfloat16* d = &g_Ap[(size_t)(t * BB + b) * KP];
        d[h] = hi; d[512 + h] = hi; d[1024 + h] = lo;
    }
}

// ---------------- the persistent recurrence kernel ----------------
__global__ void __launch_bounds__(256) k_rec(
    const int* __restrict__ cur, const int* __restrict__ gtr,
    const float* __restrict__ emb, const float* __restrict__ attn_W,
    const float* __restrict__ enc, const float* __restrict__ bi,
    const float* __restrict__ bh)
{
    __shared__ __align__(16) char smraw[(2 * 64 * LDA + 2 * 128 * LDA) * 2]; // 30720 B
    int bid = blockIdx.x;

    for (int t = 0; t < TT; t++) {
        const int* tok = (t == 0) ? cur : (gtr + (size_t)(t - 1) * BB);
        // P1: attention (0-63) || gate h-part GEMMs for both layers (64-127)
        if (bid < 64) {
            ph_attn(bid, tok, emb, attn_W, enc, (float*)smraw, (float*)smraw + 2 * EE);
        } else {
            int q = bid - 64;
            int l = q >> 5, s = q & 31;
            ph_rgemm(&g_GAh[l][0][0], &g_GWh[l][0][0], 4 * HH, &g_gh[l][0][0][0],
                     s & 15, s >> 4, (KG / 32) / ZH, KG, smraw);
        }
        gridbar();
        // P2: rnn_in GEMM (cat2 @ AOW^T)
        ph_rgemm(&g_A1[0][0], &g_AOW[0][0], EE, &g_rp[0][0][0],
                 bid & 3, bid >> 2, 3, KR, smraw);
        gridbar();
        // P3: relu + split
        ph_comb();
        gridbar();
        // P4: gates l0 x-part
        ph_rgemm(&g_GAx[0][0][0], &g_GWx[0][0][0], 4 * HH, &g_gp[0][0][0],
                 bid & 15, bid >> 4, (KG / 32) / ZG, KG, smraw);
        gridbar();
        ph_cell(0, t, bi, bh);
        gridbar();
        // P6: gates l1 x-part
        ph_rgemm(&g_GAx[1][0][0], &g_GWx[1][0][0], 4 * HH, &g_gp[0][0][0],
                 bid & 15, bid >> 4, (KG / 32) / ZG, KG, smraw);
        gridbar();
        ph_cell(1, t, bi, bh);
        gridbar();
    }
}

// ---------------- one-time weight splits ----------------
__global__ void __launch_bounds__(256) k_cvtW(const float* __restrict__ W) {
    size_t t = (size_t)blockIdx.x * 256 + threadIdx.x;   // VV*512/4
    size_t row = t >> 7;
    int kq = (int)(t & 127) * 4;
    float4 v = *(const float4*)(W + row * 512 + kq);
    __nv_bfloat16 h0, l0, h1, l1, h2, l2, h3, l3;
    bsplit(v.x, h0, l0); bsplit(v.y, h1, l1); bsplit(v.z, h2, l2); bsplit(v.w, h3, l3);
    __nv_bfloat16* d = &g_Wp[row * KP + kq];
    *(__nv_bfloat162*)(d)        = __nv_bfloat162(h0, h1);
    *(__nv_bfloat162*)(d + 2)    = __nv_bfloat162(h2, h3);
    *(__nv_bfloat162*)(d + 512)  = __nv_bfloat162(l0, l1);
    *(__nv_bfloat162*)(d + 514)  = __nv_bfloat162(l2, l3);
    *(__nv_bfloat162*)(d + 1024) = __nv_bfloat162(h0, h1);
    *(__nv_bfloat162*)(d + 1026) = __nv_bfloat162(h2, h3);
}

// Wi -> GWx, Wh -> GWh: per row over K=512 -> [hi(512)|lo(512)|hi(512)]
__global__ void __launch_bounds__(256) k_cvtGW(const float* __restrict__ Wi,
                                               const float* __restrict__ Wh) {
    size_t t = (size_t)blockIdx.x * 256 + threadIdx.x;   // NL*2048*128
    if (t >= (size_t)NL * 4 * HH * 128) return;
    int l = (int)(t >> 18);
    size_t r = t & ((1u << 18) - 1);
    int n = (int)(r >> 7);
    int k = (int)(r & 127) * 4;

    float4 v = *(const float4*)(Wi + ((size_t)l * 4 * HH + n) * 512 + k);
    __nv_bfloat16 h0, l0, h1, l1, h2, l2, h3, l3;
    bsplit(v.x, h0, l0); bsplit(v.y, h1, l1); bsplit(v.z, h2, l2); bsplit(v.w, h3, l3);
    __nv_bfloat16* d = &g_GWx[l][n][k];
    *(__nv_bfloat162*)(d)        = __nv_bfloat162(h0, h1);
    *(__nv_bfloat162*)(d + 2)    = __nv_bfloat162(h2, h3);
    *(__nv_bfloat162*)(d + 512)  = __nv_bfloat162(l0, l1);
    *(__nv_bfloat162*)(d + 514)  = __nv_bfloat162(l2, l3);
    *(__nv_bfloat162*)(d + 1024) = __nv_bfloat162(h0, h1);
    *(__nv_bfloat162*)(d + 1026) = __nv_bfloat162(h2, h3);

    v = *(const float4*)(Wh + ((size_t)l * 4 * HH + n) * 512 + k);
    bsplit(v.x, h0, l0); bsplit(v.y, h1, l1); bsplit(v.z, h2, l2); bsplit(v.w, h3, l3);
    d = &g_GWh[l][n][k];
    *(__nv_bfloat162*)(d)        = __nv_bfloat162(h0, h1);
    *(__nv_bfloat162*)(d + 2)    = __nv_bfloat162(h2, h3);
    *(__nv_bfloat162*)(d + 512)  = __nv_bfloat162(l0, l1);
    *(__nv_bfloat162*)(d + 514)  = __nv_bfloat162(l2, l3);
    *(__nv_bfloat162*)(d + 1024) = __nv_bfloat162(h0, h1);
    *(__nv_bfloat162*)(d + 1026) = __nv_bfloat162(h2, h3);
}

__global__ void __launch_bounds__(256) k_cvtAOW(const float* __restrict__ W) {
    size_t t = (size_t)blockIdx.x * 256 + threadIdx.x;
    if (t >= (size_t)EE * 1024 / 4) return;
    int row = (int)(t >> 8);
    int k = (int)(t & 255) * 4;
    float4 v = *(const float4*)(W + (size_t)row * 1024 + k);
    __nv_bfloat16 h0, l0, h1, l1, h2, l2, h3, l3;
    bsplit(v.x, h0, l0); bsplit(v.y, h1, l1); bsplit(v.z, h2, l2); bsplit(v.w, h3, l3);
    __nv_bfloat16* d = &g_AOW[row][k];
    *(__nv_bfloat162*)(d)        = __nv_bfloat162(h0, h1);
    *(__nv_bfloat162*)(d + 2)    = __nv_bfloat162(h2, h3);
    *(__nv_bfloat162*)(d + 1024) = __nv_bfloat162(l0, l1);
    *(__nv_bfloat162*)(d + 1026) = __nv_bfloat162(l2, l3);
    *(__nv_bfloat162*)(d + 2048) = __nv_bfloat162(h0, h1);
    *(__nv_bfloat162*)(d + 2050) = __nv_bfloat162(h2, h3);
}

// ---------------- vocab GEMM: cp.async double-buffered pipeline ----------------
__global__ void __launch_bounds__(256) k_vocab(const float* __restrict__ gen_b,
                                               float* __restrict__ out)
{
    __shared__ __nv_bfloat16 sA[2][128 * LDA];
    __shared__ __nv_bfloat16 sB[2][128 * LDA];

    int tid = threadIdx.x;
    int wid = tid >> 5, lane = tid & 31;
    int n0 = blockIdx.x * 128;
    int m0 = blockIdx.y * 128;
    int wm = (wid & 3) * 32;
    int wn = (wid >> 2) * 64;

    float acc[2][8][4];
    #pragma unroll
    for (int a = 0; a < 2; a++)
        #pragma unroll
        for (int b = 0; b < 8; b++)
            #pragma unroll
            for (int q = 0; q < 4; q++) acc[a][b][q] = 0.f;

    int lrow = tid >> 2;
    int lseg = (tid & 3) * 8;
    const __nv_bfloat16* Ag0 = g_Ap + (size_t)(m0 + lrow)      * KP + lseg;
    const __nv_bfloat16* Ag1 = g_Ap + (size_t)(m0 + lrow + 64) * KP + lseg;
    const __nv_bfloat16* Bg0 = g_Wp + (size_t)(n0 + lrow)      * KP + lseg;
    const __nv_bfloat16* Bg1 = g_Wp + (size_t)(n0 + lrow + 64) * KP + lseg;
    uint32_t sa0 = smem_u32(&sA[0][lrow * LDA + lseg]);
    uint32_t sa1 = smem_u32(&sA[0][(lrow + 64) * LDA + lseg]);
    uint32_t sb0 = smem_u32(&sB[0][lrow * LDA + lseg]);
    uint32_t sb1 = smem_u32(&sB[0][(lrow + 64) * LDA + lseg]);
    const uint32_t BUF = 128 * LDA * 2;   // bytes per buffer

    // preload chunk 0 into buffer 0
    CP_ASYNC16(sa0, Ag0);
    CP_ASYNC16(sa1, Ag1);
    CP_ASYNC16(sb0, Bg0);
    CP_ASYNC16(sb1, Bg1);
    CP_COMMIT();
    CP_WAIT0();
    __syncthreads();

    const int NCH = KP / 32;   // 48
    for (int c = 0; c < NCH; c++) {
        int cur = c & 1;
        if (c + 1 < NCH) {   // async-fill the other buffer while computing this one
            uint32_t off = (uint32_t)((c + 1) & 1) * BUF;
            int go = (c + 1) * 32;
            CP_ASYNC16(sa0 + off, Ag0 + go);
            CP_ASYNC16(sa1 + off, Ag1 + go);
            CP_ASYNC16(sb0 + off, Bg0 + go);
            CP_ASYNC16(sb1 + off, Bg1 + go);
            CP_COMMIT();
        }

        #pragma unroll
        for (int ks = 0; ks < 2; ks++) {
            int kc = ks * 16;
            uint32_t afr[2][4];
            #pragma unroll
            for (int am = 0; am < 2; am++) {
                int row = wm + am * 16 + (lane & 15);
                int col = kc + (lane >> 4) * 8;
                uint32_t addr = smem_u32(&sA[cur][row * LDA + col]);
                asm volatile("ldmatrix.sync.aligned.m8n8.x4.shared.b16 {%0,%1,%2,%3}, [%4];"
                    : "=r"(afr[am][0]), "=r"(afr[am][1]), "=r"(afr[am][2]), "=r"(afr[am][3])
                    : "r"(addr));
            }
            uint32_t bfr[4][4];
            #pragma unroll
            for (int bn = 0; bn < 4; bn++) {
                int sub = lane >> 3;
                int row = wn + bn * 16 + (sub >> 1) * 8 + (lane & 7);
                int col = kc + (sub & 1) * 8;
                uint32_t addr = smem_u32(&sB[cur][row * LDA + col]);
                asm volatile("ldmatrix.sync.aligned.m8n8.x4.shared.b16 {%0,%1,%2,%3}, [%4];"
                    : "=r"(bfr[bn][0]), "=r"(bfr[bn][1]), "=r"(bfr[bn][2]), "=r"(bfr[bn][3])
                    : "r"(addr));
            }
            #pragma unroll
            for (int am = 0; am < 2; am++) {
                #pragma unroll
                for (int bn = 0; bn < 8; bn++) {
                    uint32_t b0 = bfr[bn >> 1][(bn & 1) * 2];
                    uint32_t b1 = bfr[bn >> 1][(bn & 1) * 2 + 1];
                    asm volatile(
                        "mma.sync.aligned.m16n8k16.row.col.f32.bf16.bf16.f32 "
                        "{%0,%1,%2,%3}, {%4,%5,%6,%7}, {%8,%9}, {%0,%1,%2,%3};"
                        : "+f"(acc[am][bn][0]), "+f"(acc[am][bn][1]),
                          "+f"(acc[am][bn][2]), "+f"(acc[am][bn][3])
                        : "r"(afr[am][0]), "r"(afr[am][1]), "r"(afr[am][2]), "r"(afr[am][3]),
                          "r"(b0), "r"(b1));
                }
            }
        }
        if (c + 1 < NCH) CP_WAIT0();
        __syncthreads();
    }

    int group = lane >> 2, tq = (lane & 3) * 2;
    #pragma unroll
    for (int am = 0; am < 2; am++) {
        #pragma unroll
        for (int bn = 0; bn < 8; bn++) {
            int r0 = m0 + wm + am * 16 + group;
            int cx = n0 + wn + bn * 8 + tq;
            float b0 = gen_b[cx], b1 = gen_b[cx + 1];
            float2 v0 = { acc[am][bn][0] + b0, acc[am][bn][1] + b1 };
            float2 v1 = { acc[am][bn][2] + b0, acc[am][bn][3] + b1 };
            *(float2*)&out[(size_t)r0 * VV + cx]       = v0;
            *(float2*)&out[(size_t)(r0 + 8) * VV + cx] = v1;
        }
    }
}

// ---------------- final state copy ----------------
__global__ void k_fin(float* __restrict__ out) {
    int i = blockIdx.x * 256 + threadIdx.x;
    int n = NL * BB * HH;
    if (i < n)           out[i] = ((const float*)g_h)[i];
    else if (i < 2 * n)  out[i] = ((const float*)g_c)[i - n];
}

// ---------------- launch ----------------
extern "C" void kernel_launch(void* const* d_in, const int* in_sizes, int n_in,
                              void* d_out, int out_size) {
    int o = (n_in >= 15) ? 1 : 0;   // optional scalar 'length'
    const int*   cur        = (const int*)  d_in[0];
    const float* h0         = (const float*)d_in[1];
    const float* c0         = (const float*)d_in[2];
    const float* enc        = (const float*)d_in[3];
    const int*   gtr        = (const int*)  d_in[4];
    const float* emb        = (const float*)d_in[5 + o];
    const float* attn_W     = (const float*)d_in[6 + o];
    const float* attn_out_W = (const float*)d_in[7 + o];
    const float* Wi         = (const float*)d_in[8 + o];
    const float* Wh         = (const float*)d_in[9 + o];
    const float* bi         = (const float*)d_in[10 + o];
    const float* bh         = (const float*)d_in[11 + o];
    const float* gen_W      = (const float*)d_in[12 + o];
    const float* gen_b      = (const float*)d_in[13 + o];
    float* out = (float*)d_out;

    k_init<<<(NL * BB * HH + 255) / 256, 256>>>(h0, c0);
    k_cvtW<<<(VV * 512 / 4 + 255) / 256, 256>>>(gen_W);
    k_cvtGW<<<((NL * 4 * HH * 128) + 255) / 256, 256>>>(Wi, Wh);
    k_cvtAOW<<<((EE * 1024 / 4) + 255) / 256, 256>>>(attn_out_W);

    // entire 32-step recurrence in one persistent kernel
    k_rec<<<NBLK, 256>>>(cur, gtr, emb, attn_W, enc, bi, bh);

    // vocab GEMM over all steps' top-layer h
    k_vocab<<<dim3(VV / 128, (TT * BB) / 128), 256>>>(gen_b, out);

    size_t sn = (size_t)TT * BB * VV;
    if ((size_t)out_size >= sn + (size_t)2 * NL * BB * HH)
        k_fin<<<(2 * NL * BB * HH + 255) / 256, 256>>>(out + sn);
}

// round 17
// speedup vs baseline: 1.5001x; 1.1226x over previous
#include <cuda_runtime.h>
#include <cuda_bf16.h>
#include <cuda_fp16.h>
#include <math.h>
#include <stdint.h>

// ---------------- problem constants ----------------
#define TT  32      // timesteps
#define BB  64      // batch
#define HH  512     // hidden
#define EE  512     // embed
#define MLL 64      // encoder length
#define VV  32000   // vocab
#define NL  2       // lstm layers
#define KP  1024    // vocab split-fp16 K (2 x 512: [Ah|Ah] . [Wh|Wl])
#define KR  3072    // cat2 split-bf16 K (3 x 1024)
#define KG  1536    // gate-half split-bf16 K (3 x 512)
#define LDA 40      // padded smem row (16-bit units)
#define NBLK 128    // persistent-kernel grid (co-resident)
#define ZR  32      // rnn_in K-split planes
#define ZG  8       // gate x-part K-split planes
#define ZH  2       // gate h-part K-split planes

// ---------------- persistent device state ----------------
__device__ float g_h[NL][BB][HH];
__device__ float g_c[NL][BB][HH];
__device__ float g_rp[ZR][BB][EE];            // rnn_in K-split partials
__device__ float g_gp[ZG][BB][4 * HH];        // gate x-part partials
__device__ float g_gh[NL][ZH][BB][4 * HH];    // gate h-part partials
__device__ __nv_bfloat16 g_A1[BB][KR];        // cat2 split [emb|ctx]
__device__ __nv_bfloat16 g_GAx[NL][BB][KG];   // gate x-input split per layer
__device__ __nv_bfloat16 g_GAh[NL][BB][KG];   // gate h-input split per layer
__device__ __nv_bfloat16 g_AOW[EE][KR];       // attn_out_W split
__device__ __nv_bfloat16 g_GWx[NL][4 * HH][KG];  // Wi_l split
__device__ __nv_bfloat16 g_GWh[NL][4 * HH][KG];  // Wh_l split
__device__ __half g_Ap[(size_t)TT * BB * KP];    // vocab A' = [Ah|Ah] fp16
__device__ __half g_Wp[(size_t)VV * KP];         // vocab W' = [Wh|Wl] fp16

// software grid barrier (zero-init; counter self-resets)
__device__ unsigned g_barc;
__device__ volatile unsigned g_barg;

__device__ __forceinline__ float sigf(float x) { return 1.0f / (1.0f + expf(-x)); }

__device__ __forceinline__ uint32_t smem_u32(const void* p) {
    uint32_t a;
    asm("{ .reg .u64 t; cvta.to.shared.u64 t, %1; cvt.u32.u64 %0, t; }" : "=r"(a) : "l"(p));
    return a;
}

__device__ __forceinline__ void bsplit(float v, __nv_bfloat16& hi, __nv_bfloat16& lo) {
    hi = __float2bfloat16_rn(v);
    lo = __float2bfloat16_rn(v - __bfloat162float(hi));
}
__device__ __forceinline__ void hsplit(float v, __half& hi, __half& lo) {
    hi = __float2half_rn(v);
    lo = __float2half_rn(v - __half2float(hi));
}

// grid barrier: fence -> arrive -> last flips generation; others hot-spin on L2.
__device__ __forceinline__ void gridbar() {
    __syncthreads();
    if (threadIdx.x == 0) {
        unsigned g = g_barg;
        __threadfence();
        if (atomicAdd(&g_barc, 1u) == NBLK - 1) {
            g_barc = 0;
            __threadfence();
            g_barg = g + 1;
        } else {
            while (g_barg == g) {}
            __threadfence();
        }
    }
    __syncthreads();
}

// cp.async helpers (16B)
#define CP_ASYNC16(dst, src) \
    asm volatile("cp.async.cg.shared.global [%0], [%1], 16;" :: "r"(dst), "l"(src))
#define CP_COMMIT()  asm volatile("cp.async.commit_group;" ::: "memory")
#define CP_WAIT0()   asm volatile("cp.async.wait_group 0;" ::: "memory")

// ---------------- init: state copy + h split into GAh ----------------
__global__ void k_init(const float* __restrict__ h0, const float* __restrict__ c0) {
    int i = blockIdx.x * 256 + threadIdx.x;
    if (i < NL * BB * HH) {
        ((float*)g_h)[i] = h0[i];
        ((float*)g_c)[i] = c0[i];
        int l = i >> 15, r = i & 32767;
        int b = r >> 9, h = r & 511;
        __nv_bfloat16 hi, lo;
        bsplit(h0[i], hi, lo);
        g_GAh[l][b][h] = hi; g_GAh[l][b][512 + h] = hi; g_GAh[l][b][1024 + h] = lo;
    }
}

// ================= persistent-kernel phases =================

__device__ void ph_attn(int b, const int* __restrict__ tok,
                        const float* __restrict__ emb,
                        const float* __restrict__ attn_W,
                        const float* __restrict__ enc,
                        float* av, float* sc)
{
    int tid = threadIdx.x;
    int t = tok[b];
    const float* er = emb + (size_t)t * EE;
    for (int i = tid; i < EE; i += 256) {
        float v = er[i];
        av[i] = v;
        __nv_bfloat16 hi, lo;
        bsplit(v, hi, lo);
        g_A1[b][i] = hi; g_A1[b][1024 + i] = hi; g_A1[b][2048 + i] = lo;
    }
    const float* hr = &g_h[NL - 1][b][0];
    for (int i = tid; i < HH; i += 256) av[EE + i] = hr[i];
    __syncthreads();

    int w = tid >> 5, lane = tid & 31;
    for (int m = w; m < MLL; m += 8) {
        const float* wr = attn_W + (size_t)m * (EE + HH);
        float s = 0.f;
        #pragma unroll 8
        for (int k = lane; k < EE + HH; k += 32) s = fmaf(av[k], wr[k], s);
        #pragma unroll
        for (int o = 16; o; o >>= 1) s += __shfl_xor_sync(0xffffffffu, s, o);
        if (lane == 0) sc[m] = s;
    }
    __syncthreads();

    if (tid < 32) {
        float a0 = sc[tid], a1 = sc[tid + 32];
        float m = fmaxf(a0, a1);
        #pragma unroll
        for (int o = 16; o; o >>= 1) m = fmaxf(m, __shfl_xor_sync(0xffffffffu, m, o));
        float e0 = expf(a0 - m), e1 = expf(a1 - m);
        float s = e0 + e1;
        #pragma unroll
        for (int o = 16; o; o >>= 1) s += __shfl_xor_sync(0xffffffffu, s, o);
        float inv = 1.0f / s;
        sc[tid] = e0 * inv;
        sc[tid + 32] = e1 * inv;
    }
    __syncthreads();

    for (int h = tid; h < HH; h += 256) {
        float acc = 0.f;
        #pragma unroll 8
        for (int m = 0; m < MLL; m++)
            acc = fmaf(sc[m], enc[((size_t)m * BB + b) * HH + h], acc);
        __nv_bfloat16 hi, lo;
        bsplit(acc, hi, lo);
        g_A1[b][512 + h] = hi; g_A1[b][1536 + h] = hi; g_A1[b][2560 + h] = lo;
    }
    __syncthreads();
}

// K-split GEMM slice: Cp[z][64][Ntot] = A'[64, kst] @ W'[Ntot, kst]^T (ntile cols)
__device__ void ph_rgemm(const __nv_bfloat16* __restrict__ A,
                         const __nv_bfloat16* __restrict__ W,
                         int Ntot, float* __restrict__ Cp,
                         int ntile, int z, int nch, int kst, char* smraw)
{
    __nv_bfloat16* sA = (__nv_bfloat16*)smraw;     // [2][64*LDA]
    __nv_bfloat16* sB = sA + 2 * 64 * LDA;         // [2][128*LDA]

    int tid = threadIdx.x;
    int wid = tid >> 5, lane = tid & 31;
    int n0 = ntile * 128;
    int wm = (wid & 3) * 16;
    int wn = (wid >> 2) * 64;
    int c0 = z * nch;

    float acc[8][4];
    #pragma unroll
    for (int b = 0; b < 8; b++)
        #pragma unroll
        for (int q = 0; q < 4; q++) acc[b][q] = 0.f;

    int lrow = tid >> 2;
    int lseg = (tid & 3) * 8;
    const __nv_bfloat16* Ag  = A + (size_t)lrow * kst + c0 * 32 + lseg;
    const __nv_bfloat16* Bg0 = W + (size_t)(n0 + lrow)      * kst + c0 * 32 + lseg;
    const __nv_bfloat16* Bg1 = W + (size_t)(n0 + lrow + 64) * kst + c0 * 32 + lseg;
    int srA = lrow * LDA + lseg;
    int sr1 = (lrow + 64) * LDA + lseg;

    float4 ra  = *(const float4*)Ag;
    float4 rb0 = *(const float4*)Bg0;
    float4 rb1 = *(const float4*)Bg1;

    for (int c = 0; c < nch; c++) {
        int cur = c & 1;
        *(float4*)&sA[cur * 64 * LDA + srA]  = ra;
        *(float4*)&sB[cur * 128 * LDA + srA] = rb0;
        *(float4*)&sB[cur * 128 * LDA + sr1] = rb1;
        if (c + 1 < nch) {
            ra  = *(const float4*)(Ag  + (c + 1) * 32);
            rb0 = *(const float4*)(Bg0 + (c + 1) * 32);
            rb1 = *(const float4*)(Bg1 + (c + 1) * 32);
        }
        __syncthreads();

        #pragma unroll
        for (int ks = 0; ks < 2; ks++) {
            int kc = ks * 16;
            uint32_t afr[4];
            {
                int row = wm + (lane & 15);
                int col = kc + (lane >> 4) * 8;
                uint32_t addr = smem_u32(&sA[cur * 64 * LDA + row * LDA + col]);
                asm volatile("ldmatrix.sync.aligned.m8n8.x4.shared.b16 {%0,%1,%2,%3}, [%4];"
                    : "=r"(afr[0]), "=r"(afr[1]), "=r"(afr[2]), "=r"(afr[3]) : "r"(addr));
            }
            uint32_t bfr[4][4];
            #pragma unroll
            for (int bn = 0; bn < 4; bn++) {
                int sub = lane >> 3;
                int row = wn + bn * 16 + (sub >> 1) * 8 + (lane & 7);
                int col = kc + (sub & 1) * 8;
                uint32_t addr = smem_u32(&sB[cur * 128 * LDA + row * LDA + col]);
                asm volatile("ldmatrix.sync.aligned.m8n8.x4.shared.b16 {%0,%1,%2,%3}, [%4];"
                    : "=r"(bfr[bn][0]), "=r"(bfr[bn][1]), "=r"(bfr[bn][2]), "=r"(bfr[bn][3])
                    : "r"(addr));
            }
            #pragma unroll
            for (int bn = 0; bn < 8; bn++) {
                uint32_t b0 = bfr[bn >> 1][(bn & 1) * 2];
                uint32_t b1 = bfr[bn >> 1][(bn & 1) * 2 + 1];
                asm volatile(
                    "mma.sync.aligned.m16n8k16.row.col.f32.bf16.bf16.f32 "
                    "{%0,%1,%2,%3}, {%4,%5,%6,%7}, {%8,%9}, {%0,%1,%2,%3};"
                    : "+f"(acc[bn][0]), "+f"(acc[bn][1]), "+f"(acc[bn][2]), "+f"(acc[bn][3])
                    : "r"(afr[0]), "r"(afr[1]), "r"(afr[2]), "r"(afr[3]), "r"(b0), "r"(b1));
            }
        }
        __syncthreads();
    }

    int group = lane >> 2, tq = (lane & 3) * 2;
    float* Co = Cp + (size_t)z * 64 * Ntot;
    #pragma unroll
    for (int bn = 0; bn < 8; bn++) {
        int r0 = wm + group;
        int cx = n0 + wn + bn * 8 + tq;
        float2 v0 = { acc[bn][0], acc[bn][1] };
        float2 v1 = { acc[bn][2], acc[bn][3] };
        *(float2*)&Co[(size_t)r0 * Ntot + cx]       = v0;
        *(float2*)&Co[(size_t)(r0 + 8) * Ntot + cx] = v1;
    }
}

// sum rnn_in partials (+relu) -> split into g_GAx[0]
__device__ void ph_comb() {
    int i = blockIdx.x * 256 + threadIdx.x;   // BB*EE = 32768
    int b = i >> 9, col = i & 511;
    const float* p = (const float*)g_rp;
    float s = 0.f;
    #pragma unroll
    for (int q = 0; q < ZR; q++) s += p[(size_t)q * BB * EE + i];
    s = fmaxf(s, 0.0f);
    __nv_bfloat16 hi, lo;
    bsplit(s, hi, lo);
    g_GAx[0][b][col] = hi; g_GAx[0][b][512 + col] = hi; g_GAx[0][b][1024 + col] = lo;
}

// LSTM cell layer l at step t
__device__ void ph_cell(int l, int t, const float* __restrict__ bi,
                        const float* __restrict__ bh) {
    int idx = blockIdx.x * 256 + threadIdx.x;  // BB*HH
    int b = idx >> 9, h = idx & 511;
    float gi = 0.f, gf = 0.f, gg = 0.f, go = 0.f;
    #pragma unroll
    for (int s = 0; s < ZG; s++) {
        gi += g_gp[s][b][h];
        gf += g_gp[s][b][512 + h];
        gg += g_gp[s][b][1024 + h];
        go += g_gp[s][b][1536 + h];
    }
    #pragma unroll
    for (int s = 0; s < ZH; s++) {
        gi += g_gh[l][s][b][h];
        gf += g_gh[l][s][b][512 + h];
        gg += g_gh[l][s][b][1024 + h];
        go += g_gh[l][s][b][1536 + h];
    }
    const float* bip = bi + (size_t)l * 4 * HH;
    const float* bhp = bh + (size_t)l * 4 * HH;
    gi += bip[h]        + bhp[h];
    gf += bip[512 + h]  + bhp[512 + h];
    gg += bip[1024 + h] + bhp[1024 + h];
    go += bip[1536 + h] + bhp[1536 + h];

    float c  = g_c[l][b][h];
    float cn = sigf(gf) * c + sigf(gi) * tanhf(gg);
    float hn = sigf(go) * tanhf(cn);
    g_c[l][b][h] = cn;
    g_h[l][b][h] = hn;

    __nv_bfloat16 hi, lo;
    bsplit(hn, hi, lo);
    if (l == 0) {
        g_GAx[1][b][h] = hi; g_GAx[1][b][512 + h] = hi; g_GAx[1][b][1024 + h] = lo;
        g_GAh[0][b][h] = hi; g_GAh[0][b][512 + h] = hi; g_GAh[0][b][1024 + h] = lo;
    } else {
        g_GAh[1][b][h] = hi; g_GAh[1][b][512 + h] = hi; g_GAh[1][b][1024 + h] = lo;
        // vocab A' row: fp16 hi duplicated over both K segments
        __half hh = __float2half_rn(hn);
        __half* d = &g_Ap[(size_t)(t * BB + b) * KP];
        d[h] = hh; d[512 + h] = hh;
    }
}

// ---------------- the persistent recurrence kernel ----------------
__global__ void __launch_bounds__(256) k_rec(
    const int* __restrict__ cur, const int* __restrict__ gtr,
    const float* __restrict__ emb, const float* __restrict__ attn_W,
    const float* __restrict__ enc, const float* __restrict__ bi,
    const float* __restrict__ bh)
{
    __shared__ __align__(16) char smraw[(2 * 64 * LDA + 2 * 128 * LDA) * 2]; // 30720 B
    int bid = blockIdx.x;

    for (int t = 0; t < TT; t++) {
        const int* tok = (t == 0) ? cur : (gtr + (size_t)(t - 1) * BB);
        // P1: attention (0-63) || gate h-part GEMMs for both layers (64-127)
        if (bid < 64) {
            ph_attn(bid, tok, emb, attn_W, enc, (float*)smraw, (float*)smraw + 2 * EE);
        } else {
            int q = bid - 64;
            int l = q >> 5, s = q & 31;
            ph_rgemm(&g_GAh[l][0][0], &g_GWh[l][0][0], 4 * HH, &g_gh[l][0][0][0],
                     s & 15, s >> 4, (KG / 32) / ZH, KG, smraw);
        }
        gridbar();
        // P2: rnn_in GEMM (cat2 @ AOW^T)
        ph_rgemm(&g_A1[0][0], &g_AOW[0][0], EE, &g_rp[0][0][0],
                 bid & 3, bid >> 2, 3, KR, smraw);
        gridbar();
        // P3: relu + split
        ph_comb();
        gridbar();
        // P4: gates l0 x-part
        ph_rgemm(&g_GAx[0][0][0], &g_GWx[0][0][0], 4 * HH, &g_gp[0][0][0],
                 bid & 15, bid >> 4, (KG / 32) / ZG, KG, smraw);
        gridbar();
        ph_cell(0, t, bi, bh);
        gridbar();
        // P6: gates l1 x-part
        ph_rgemm(&g_GAx[1][0][0], &g_GWx[1][0][0], 4 * HH, &g_gp[0][0][0],
                 bid & 15, bid >> 4, (KG / 32) / ZG, KG, smraw);
        gridbar();
        ph_cell(1, t, bi, bh);
        gridbar();
    }
}

// ---------------- one-time weight splits ----------------
// gen_W -> g_Wp (fp16 2-term): [Wh(512) | Wl(512)]
__global__ void __launch_bounds__(256) k_cvtW(const float* __restrict__ W) {
    size_t t = (size_t)blockIdx.x * 256 + threadIdx.x;   // VV*512/4
    size_t row = t >> 7;
    int kq = (int)(t & 127) * 4;
    float4 v = *(const float4*)(W + row * 512 + kq);
    __half h0, l0, h1, l1, h2, l2, h3, l3;
    hsplit(v.x, h0, l0); hsplit(v.y, h1, l1); hsplit(v.z, h2, l2); hsplit(v.w, h3, l3);
    __half* d = &g_Wp[row * KP + kq];
    *(__half2*)(d)       = __half2(h0, h1);
    *(__half2*)(d + 2)   = __half2(h2, h3);
    *(__half2*)(d + 512) = __half2(l0, l1);
    *(__half2*)(d + 514) = __half2(l2, l3);
}

// Wi -> GWx, Wh -> GWh: per row over K=512 -> [hi(512)|lo(512)|hi(512)] bf16
__global__ void __launch_bounds__(256) k_cvtGW(const float* __restrict__ Wi,
                                               const float* __restrict__ Wh) {
    size_t t = (size_t)blockIdx.x * 256 + threadIdx.x;   // NL*2048*128
    if (t >= (size_t)NL * 4 * HH * 128) return;
    int l = (int)(t >> 18);
    size_t r = t & ((1u << 18) - 1);
    int n = (int)(r >> 7);
    int k = (int)(r & 127) * 4;

    float4 v = *(const float4*)(Wi + ((size_t)l * 4 * HH + n) * 512 + k);
    __nv_bfloat16 h0, l0, h1, l1, h2, l2, h3, l3;
    bsplit(v.x, h0, l0); bsplit(v.y, h1, l1); bsplit(v.z, h2, l2); bsplit(v.w, h3, l3);
    __nv_bfloat16* d = &g_GWx[l][n][k];
    *(__nv_bfloat162*)(d)        = __nv_bfloat162(h0, h1);
    *(__nv_bfloat162*)(d + 2)    = __nv_bfloat162(h2, h3);
    *(__nv_bfloat162*)(d + 512)  = __nv_bfloat162(l0, l1);
    *(__nv_bfloat162*)(d + 514)  = __nv_bfloat162(l2, l3);
    *(__nv_bfloat162*)(d + 1024) = __nv_bfloat162(h0, h1);
    *(__nv_bfloat162*)(d + 1026) = __nv_bfloat162(h2, h3);

    v = *(const float4*)(Wh + ((size_t)l * 4 * HH + n) * 512 + k);
    bsplit(v.x, h0, l0); bsplit(v.y, h1, l1); bsplit(v.z, h2, l2); bsplit(v.w, h3, l3);
    d = &g_GWh[l][n][k];
    *(__nv_bfloat162*)(d)        = __nv_bfloat162(h0, h1);
    *(__nv_bfloat162*)(d + 2)    = __nv_bfloat162(h2, h3);
    *(__nv_bfloat162*)(d + 512)  = __nv_bfloat162(l0, l1);
    *(__nv_bfloat162*)(d + 514)  = __nv_bfloat162(l2, l3);
    *(__nv_bfloat162*)(d + 1024) = __nv_bfloat162(h0, h1);
    *(__nv_bfloat162*)(d + 1026) = __nv_bfloat162(h2, h3);
}

__global__ void __launch_bounds__(256) k_cvtAOW(const float* __restrict__ W) {
    size_t t = (size_t)blockIdx.x * 256 + threadIdx.x;
    if (t >= (size_t)EE * 1024 / 4) return;
    int row = (int)(t >> 8);
    int k = (int)(t & 255) * 4;
    float4 v = *(const float4*)(W + (size_t)row * 1024 + k);
    __nv_bfloat16 h0, l0, h1, l1, h2, l2, h3, l3;
    bsplit(v.x, h0, l0); bsplit(v.y, h1, l1); bsplit(v.z, h2, l2); bsplit(v.w, h3, l3);
    __nv_bfloat16* d = &g_AOW[row][k];
    *(__nv_bfloat162*)(d)        = __nv_bfloat162(h0, h1);
    *(__nv_bfloat162*)(d + 2)    = __nv_bfloat162(h2, h3);
    *(__nv_bfloat162*)(d + 1024) = __nv_bfloat162(l0, l1);
    *(__nv_bfloat162*)(d + 1026) = __nv_bfloat162(l2, l3);
    *(__nv_bfloat162*)(d + 2048) = __nv_bfloat162(h0, h1);
    *(__nv_bfloat162*)(d + 2050) = __nv_bfloat162(h2, h3);
}

// ---------------- vocab GEMM: fp16 2-term, cp.async double-buffered ----------------
__global__ void __launch_bounds__(256) k_vocab(const float* __restrict__ gen_b,
                                               float* __restrict__ out)
{
    __shared__ __half sA[2][128 * LDA];
    __shared__ __half sB[2][128 * LDA];

    int tid = threadIdx.x;
    int wid = tid >> 5, lane = tid & 31;
    int n0 = blockIdx.x * 128;
    int m0 = blockIdx.y * 128;
    int wm = (wid & 3) * 32;
    int wn = (wid >> 2) * 64;

    float acc[2][8][4];
    #pragma unroll
    for (int a = 0; a < 2; a++)
        #pragma unroll
        for (int b = 0; b < 8; b++)
            #pragma unroll
            for (int q = 0; q < 4; q++) acc[a][b][q] = 0.f;

    int lrow = tid >> 2;
    int lseg = (tid & 3) * 8;
    const __half* Ag0 = g_Ap + (size_t)(m0 + lrow)      * KP + lseg;
    const __half* Ag1 = g_Ap + (size_t)(m0 + lrow + 64) * KP + lseg;
    const __half* Bg0 = g_Wp + (size_t)(n0 + lrow)      * KP + lseg;
    const __half* Bg1 = g_Wp + (size_t)(n0 + lrow + 64) * KP + lseg;
    uint32_t sa0 = smem_u32(&sA[0][lrow * LDA + lseg]);
    uint32_t sa1 = smem_u32(&sA[0][(lrow + 64) * LDA + lseg]);
    uint32_t sb0 = smem_u32(&sB[0][lrow * LDA + lseg]);
    uint32_t sb1 = smem_u32(&sB[0][(lrow + 64) * LDA + lseg]);
    const uint32_t BUF = 128 * LDA * 2;   // bytes per buffer

    // preload chunk 0 into buffer 0
    CP_ASYNC16(sa0, Ag0);
    CP_ASYNC16(sa1, Ag1);
    CP_ASYNC16(sb0, Bg0);
    CP_ASYNC16(sb1, Bg1);
    CP_COMMIT();
    CP_WAIT0();
    __syncthreads();

    const int NCH = KP / 32;   // 32
    for (int c = 0; c < NCH; c++) {
        int cur = c & 1;
        if (c + 1 < NCH) {
            uint32_t off = (uint32_t)((c + 1) & 1) * BUF;
            int go = (c + 1) * 32;
            CP_ASYNC16(sa0 + off, Ag0 + go);
            CP_ASYNC16(sa1 + off, Ag1 + go);
            CP_ASYNC16(sb0 + off, Bg0 + go);
            CP_ASYNC16(sb1 + off, Bg1 + go);
            CP_COMMIT();
        }

        #pragma unroll
        for (int ks = 0; ks < 2; ks++) {
            int kc = ks * 16;
            uint32_t afr[2][4];
            #pragma unroll
            for (int am = 0; am < 2; am++) {
                int row = wm + am * 16 + (lane & 15);
                int col = kc + (lane >> 4) * 8;
                uint32_t addr = smem_u32(&sA[cur][row * LDA + col]);
                asm volatile("ldmatrix.sync.aligned.m8n8.x4.shared.b16 {%0,%1,%2,%3}, [%4];"
                    : "=r"(afr[am][0]), "=r"(afr[am][1]), "=r"(afr[am][2]), "=r"(afr[am][3])
                    : "r"(addr));
            }
            uint32_t bfr[4][4];
            #pragma unroll
            for (int bn = 0; bn < 4; bn++) {
                int sub = lane >> 3;
                int row = wn + bn * 16 + (sub >> 1) * 8 + (lane & 7);
                int col = kc + (sub & 1) * 8;
                uint32_t addr = smem_u32(&sB[cur][row * LDA + col]);
                asm volatile("ldmatrix.sync.aligned.m8n8.x4.shared.b16 {%0,%1,%2,%3}, [%4];"
                    : "=r"(bfr[bn][0]), "=r"(bfr[bn][1]), "=r"(bfr[bn][2]), "=r"(bfr[bn][3])
                    : "r"(addr));
            }
            #pragma unroll
            for (int am = 0; am < 2; am++) {
                #pragma unroll
                for (int bn = 0; bn < 8; bn++) {
                    uint32_t b0 = bfr[bn >> 1][(bn & 1) * 2];
                    uint32_t b1 = bfr[bn >> 1][(bn & 1) * 2 + 1];
                    asm volatile(
                        "mma.sync.aligned.m16n8k16.row.col.f32.f16.f16.f32 "
                        "{%0,%1,%2,%3}, {%4,%5,%6,%7}, {%8,%9}, {%0,%1,%2,%3};"
                        : "+f"(acc[am][bn][0]), "+f"(acc[am][bn][1]),
                          "+f"(acc[am][bn][2]), "+f"(acc[am][bn][3])
                        : "r"(afr[am][0]), "r"(afr[am][1]), "r"(afr[am][2]), "r"(afr[am][3]),
                          "r"(b0), "r"(b1));
                }
            }
        }
        if (c + 1 < NCH) CP_WAIT0();
        __syncthreads();
    }

    int group = lane >> 2, tq = (lane & 3) * 2;
    #pragma unroll
    for (int am = 0; am < 2; am++) {
        #pragma unroll
        for (int bn = 0; bn < 8; bn++) {
            int r0 = m0 + wm + am * 16 + group;
            int cx = n0 + wn + bn * 8 + tq;
            float b0 = gen_b[cx], b1 = gen_b[cx + 1];
            float2 v0 = { acc[am][bn][0] + b0, acc[am][bn][1] + b1 };
            float2 v1 = { acc[am][bn][2] + b0, acc[am][bn][3] + b1 };
            *(float2*)&out[(size_t)r0 * VV + cx]       = v0;
            *(float2*)&out[(size_t)(r0 + 8) * VV + cx] = v1;
        }
    }
}

// ---------------- final state copy ----------------
__global__ void k_fin(float* __restrict__ out) {
    int i = blockIdx.x * 256 + threadIdx.x;
    int n = NL * BB * HH;
    if (i < n)           out[i] = ((const float*)g_h)[i];
    else if (i < 2 * n)  out[i] = ((const float*)g_c)[i - n];
}

// ---------------- launch ----------------
extern "C" void kernel_launch(void* const* d_in, const int* in_sizes, int n_in,
                              void* d_out, int out_size) {
    int o = (n_in >= 15) ? 1 : 0;   // optional scalar 'length'
    const int*   cur        = (const int*)  d_in[0];
    const float* h0         = (const float*)d_in[1];
    const float* c0         = (const float*)d_in[2];
    const float* enc        = (const float*)d_in[3];
    const int*   gtr        = (const int*)  d_in[4];
    const float* emb        = (const float*)d_in[5 + o];
    const float* attn_W     = (const float*)d_in[6 + o];
    const float* attn_out_W = (const float*)d_in[7 + o];
    const float* Wi         = (const float*)d_in[8 + o];
    const float* Wh         = (const float*)d_in[9 + o];
    const float* bi         = (const float*)d_in[10 + o];
    const float* bh         = (const float*)d_in[11 + o];
    const float* gen_W      = (const float*)d_in[12 + o];
    const float* gen_b      = (const float*)d_in[13 + o];
    float* out = (float*)d_out;

    k_init<<<(NL * BB * HH + 255) / 256, 256>>>(h0, c0);
    k_cvtW<<<(VV * 512 / 4 + 255) / 256, 256>>>(gen_W);
    k_cvtGW<<<((NL * 4 * HH * 128) + 255) / 256, 256>>>(Wi, Wh);
    k_cvtAOW<<<((EE * 1024 / 4) + 255) / 256, 256>>>(attn_out_W);

    // entire 32-step recurrence in one persistent kernel
    k_rec<<<NBLK, 256>>>(cur, gtr, emb, attn_W, enc, bi, bh);

    // vocab GEMM over all steps' top-layer h (fp16 2-term, K=1024)
    k_vocab<<<dim3(VV / 128, (TT * BB) / 128), 256>>>(gen_b, out);

    size_t sn = (size_t)TT * BB * VV;
    if ((size_t)out_size >= sn + (size_t)2 * NL * BB * HH)
        k_fin<<<(2 * NL * BB * HH + 255) / 256, 256>>>(out + sn);
}